// round 10
// baseline (speedup 1.0000x reference)
#include <cuda_runtime.h>
#include <cuda_bf16.h>
#include <math.h>
#include <stdint.h>

#define BSZ 256
#define HSZ 256
#define TIN 336
#define TOUT 96
#define FSZ 32
#define PH 128   // packed uint32 words per h row (256 bf16 pairs / 2)
#define PX 16    // packed words per (b,t) of x

// ---------------- device-global scratch (allocation-free) ----------------
__device__ uint32_t g_h0hi[2][BSZ * PH], g_h0lo[2][BSZ * PH];
__device__ uint32_t g_h1hi[2][BSZ * PH], g_h1lo[2][BSZ * PH];
__device__ float g_c0[BSZ * HSZ], g_c1[BSZ * HSZ];
__device__ uint32_t g_xhi[BSZ * TIN * PX], g_xlo[BSZ * TIN * PX];
__device__ float g_Wp[4 * HSZ * HSZ];
__device__ float g_bp[4 * HSZ];
__device__ float g_h1s[(size_t)TOUT * BSZ * HSZ];

// packed bf16 hi/lo weights: [1024 packed rows][K/2 words]
__device__ uint32_t g_eWih0h[1024 * 16],  g_eWih0l[1024 * 16];
__device__ uint32_t g_eWhh0h[1024 * 128], g_eWhh0l[1024 * 128];
__device__ uint32_t g_eWih1h[1024 * 128], g_eWih1l[1024 * 128];
__device__ uint32_t g_eWhh1h[1024 * 128], g_eWhh1l[1024 * 128];
__device__ uint32_t g_dWih0h[1024 * 16],  g_dWih0l[1024 * 16];
__device__ uint32_t g_dWhh0h[1024 * 128], g_dWhh0l[1024 * 128];
__device__ uint32_t g_dWih1h[1024 * 128], g_dWih1l[1024 * 128];
__device__ uint32_t g_dWhh1h[1024 * 128], g_dWhh1l[1024 * 128];
__device__ uint32_t g_Wph[1024 * 128],    g_Wpl[1024 * 128];

// ---------------- helpers ----------------
// word j (0..7) within a k16 chunk holds pair lp = ((j&1)<<2)|(j>>1),
// i.e. pairs (q, q+4) sit at words (2q, 2q+1) -> one LDS.64 per fragment piece.
__device__ __forceinline__ int j2lp(int j) { return ((j & 1) << 2) | (j >> 1); }

__device__ __forceinline__ void split2(float v0, float v1, uint32_t& hi,
                                       uint32_t& lo) {
  __nv_bfloat16 h0 = __float2bfloat16_rn(v0);
  __nv_bfloat16 h1 = __float2bfloat16_rn(v1);
  __nv_bfloat16 l0 = __float2bfloat16_rn(v0 - __bfloat162float(h0));
  __nv_bfloat16 l1 = __float2bfloat16_rn(v1 - __bfloat162float(h1));
  __nv_bfloat162 ph = __nv_bfloat162(h0, h1);
  __nv_bfloat162 pl = __nv_bfloat162(l0, l1);
  hi = *(uint32_t*)&ph;
  lo = *(uint32_t*)&pl;
}

#define MMA_BF16(C, a0, a1, a2, a3, b0, b1)                                   \
  asm volatile(                                                               \
      "mma.sync.aligned.m16n8k16.row.col.f32.bf16.bf16.f32 "                  \
      "{%0,%1,%2,%3},{%4,%5,%6,%7},{%8,%9},{%0,%1,%2,%3};"                    \
      : "+f"(C[0]), "+f"(C[1]), "+f"(C[2]), "+f"(C[3])                        \
      : "r"(a0), "r"(a1), "r"(a2), "r"(a3), "r"(b0), "r"(b1))

// ---------------- init / preprocess ----------------
__global__ void zero_init_kernel() {
  int i = blockIdx.x * blockDim.x + threadIdx.x;   // 65536 threads
  g_c0[i] = 0.f;
  g_c1[i] = 0.f;
  if (i < BSZ * PH) {
    g_h0hi[0][i] = 0u; g_h0hi[1][i] = 0u; g_h0lo[0][i] = 0u; g_h0lo[1][i] = 0u;
    g_h1hi[0][i] = 0u; g_h1hi[1][i] = 0u; g_h1lo[0][i] = 0u; g_h1lo[1][i] = 0u;
  }
}

__global__ void wp_kernel(const float* __restrict__ Wih0,
                          const float* __restrict__ Wout) {
  __shared__ float wr[FSZ];
  int c = blockIdx.x;
  if (threadIdx.x < FSZ) wr[threadIdx.x] = Wih0[c * FSZ + threadIdx.x];
  __syncthreads();
  int k = threadIdx.x;
  float acc = 0.f;
#pragma unroll
  for (int f = 0; f < FSZ; ++f) acc += wr[f] * Wout[f * HSZ + k];
  g_Wp[c * HSZ + k] = acc;
}

__global__ void bp_kernel(const float* __restrict__ Wih0,
                          const float* __restrict__ b0,
                          const float* __restrict__ bout) {
  int c = blockIdx.x * blockDim.x + threadIdx.x;
  float acc = b0[c];
#pragma unroll
  for (int f = 0; f < FSZ; ++f) acc += Wih0[c * FSZ + f] * bout[f];
  g_bp[c] = acc;
}

// pack fp32 W[1024][K] -> packed-row bf16 hi/lo planes [1024][K/2]
__global__ void pack_w(const float* __restrict__ W, int K,
                       uint32_t* __restrict__ ohi, uint32_t* __restrict__ olo) {
  int P = K >> 1;
  int idx = blockIdx.x * 256 + threadIdx.x;
  if (idx >= 1024 * P) return;
  int pr = idx / P, w = idx % P;
  int n = pr & 63, by = pr >> 6;
  int r = (n >> 4) * 256 + by * 16 + (n & 15);
  int cch = w >> 3, j = w & 7;
  int k0 = cch * 16 + 2 * j2lp(j);
  split2(W[r * K + k0], W[r * K + k0 + 1], ohi[idx], olo[idx]);
}

__global__ void pack_x(const float* __restrict__ x) {
  int idx = blockIdx.x * 256 + threadIdx.x;   // BSZ*TIN*PX
  int w = idx & (PX - 1);
  int bt = idx >> 4;                          // b*TIN + t
  int cch = w >> 3, j = w & 7;
  int k0 = cch * 16 + 2 * j2lp(j);
  const float* src = x + (size_t)bt * FSZ + k0;
  split2(src[0], src[1], g_xhi[idx], g_xlo[idx]);
}

// ---------------- fused LSTM cell step (bf16x3 mma, pipelined) ----------------
// gates[B,4H] = A[B,2*Pa]@Wih^T + h[B,256]@Whh^T + bias, then pointwise.
// 256 threads, 8 warps (2x4), CTA tile 32 batch x 64 gate-cols, grid (8,16).
__global__ __launch_bounds__(256) void lstm_step(
    const uint32_t* __restrict__ Ahi, const uint32_t* __restrict__ Alo,
    int ldaA, int Pa,
    const uint32_t* __restrict__ W0h, const uint32_t* __restrict__ W0l,
    const uint32_t* __restrict__ Hhi, const uint32_t* __restrict__ Hlo,
    const uint32_t* __restrict__ W1h, const uint32_t* __restrict__ W1l,
    const float* __restrict__ bias, float* __restrict__ c_state,
    uint32_t* __restrict__ outHi, uint32_t* __restrict__ outLo,
    float* __restrict__ outF) {
  // buffers: per buf 1536 words: sAh 256 | sAl 256 | sWh 512 | sWl 512
  __shared__ __align__(16) uint32_t sm[3072];
  int tid = threadIdx.x;
  int row0 = blockIdx.x * 32;
  int by = blockIdx.y;
  int lane = tid & 31, wid = tid >> 5;
  int g = lane >> 2, q = lane & 3;
  int wm = (wid & 1) * 16, wn = (wid >> 1) * 16;

  W0h += (size_t)by * 64 * Pa;  W0l += (size_t)by * 64 * Pa;
  W1h += (size_t)by * 64 * PH;  W1l += (size_t)by * 64 * PH;

  float c[2][4] = {};
  int c0 = Pa >> 3;
  int N = c0 + 16;

  int ra = tid >> 3, j = tid & 7;   // A fill: row ra, word j
  int rw = tid >> 3;                // W fill: rows rw and rw+32, word j

  uint32_t rAh, rAl, rWh0, rWh1, rWl0, rWl1;
  // prefetch chunk 0 (seg 0 always exists)
  {
    rAh = Ahi[(size_t)(row0 + ra) * ldaA + j];
    rAl = Alo[(size_t)(row0 + ra) * ldaA + j];
    rWh0 = W0h[(size_t)rw * Pa + j];        rWh1 = W0h[(size_t)(rw + 32) * Pa + j];
    rWl0 = W0l[(size_t)rw * Pa + j];        rWl1 = W0l[(size_t)(rw + 32) * Pa + j];
  }
  uint32_t* sAh = sm;        uint32_t* sAl = sm + 256;
  uint32_t* sWh = sm + 512;  uint32_t* sWl = sm + 1024;
  // store chunk 0 into buf0
  sAh[ra * 8 + j] = rAh;  sAl[ra * 8 + j] = rAl;
  sWh[rw * 8 + j] = rWh0; sWh[(rw + 32) * 8 + j] = rWh1;
  sWl[rw * 8 + j] = rWl0; sWl[(rw + 32) * 8 + j] = rWl1;
  __syncthreads();

  for (int i = 0; i < N; ++i) {
    int buf = (i & 1) * 1536;
    if (i + 1 < N) {  // prefetch next chunk
      int ii = i + 1;
      if (ii < c0) {
        int off = ii * 8 + j;
        rAh = Ahi[(size_t)(row0 + ra) * ldaA + off];
        rAl = Alo[(size_t)(row0 + ra) * ldaA + off];
        rWh0 = W0h[(size_t)rw * Pa + off];  rWh1 = W0h[(size_t)(rw + 32) * Pa + off];
        rWl0 = W0l[(size_t)rw * Pa + off];  rWl1 = W0l[(size_t)(rw + 32) * Pa + off];
      } else {
        int off = (ii - c0) * 8 + j;
        rAh = Hhi[(size_t)(row0 + ra) * PH + off];
        rAl = Hlo[(size_t)(row0 + ra) * PH + off];
        rWh0 = W1h[(size_t)rw * PH + off];  rWh1 = W1h[(size_t)(rw + 32) * PH + off];
        rWl0 = W1l[(size_t)rw * PH + off];  rWl1 = W1l[(size_t)(rw + 32) * PH + off];
      }
    }
    // MMA on current buffer
    {
      const uint32_t* bAh = sm + buf;
      const uint32_t* bAl = sm + buf + 256;
      const uint32_t* bWh = sm + buf + 512;
      const uint32_t* bWl = sm + buf + 1024;
      int aoff = (wm + g) * 8 + 2 * q;
      uint2 Ah0 = *(const uint2*)&bAh[aoff];
      uint2 Ah1 = *(const uint2*)&bAh[aoff + 64];
      uint2 Al0 = *(const uint2*)&bAl[aoff];
      uint2 Al1 = *(const uint2*)&bAl[aoff + 64];
#pragma unroll
      for (int nb = 0; nb < 2; ++nb) {
        int boff = (wn + nb * 8 + g) * 8 + 2 * q;
        uint2 Bh = *(const uint2*)&bWh[boff];
        uint2 Bl = *(const uint2*)&bWl[boff];
        MMA_BF16(c[nb], Ah0.x, Ah1.x, Ah0.y, Ah1.y, Bh.x, Bh.y);
        MMA_BF16(c[nb], Ah0.x, Ah1.x, Ah0.y, Ah1.y, Bl.x, Bl.y);
        MMA_BF16(c[nb], Al0.x, Al1.x, Al0.y, Al1.y, Bh.x, Bh.y);
      }
    }
    if (i + 1 < N) {  // store prefetched chunk into other buffer
      int nbuf = ((i + 1) & 1) * 1536;
      uint32_t* nAh = sm + nbuf;
      uint32_t* nAl = sm + nbuf + 256;
      uint32_t* nWh = sm + nbuf + 512;
      uint32_t* nWl = sm + nbuf + 1024;
      nAh[ra * 8 + j] = rAh;  nAl[ra * 8 + j] = rAl;
      nWh[rw * 8 + j] = rWh0; nWh[(rw + 32) * 8 + j] = rWh1;
      nWl[rw * 8 + j] = rWl0; nWl[(rw + 32) * 8 + j] = rWl1;
      __syncthreads();
    }
  }
  __syncthreads();

  // ---- exchange gates via SMEM (reuse sm as float) ----
  float* gsm = (float*)sm;  // 32 x 65
#pragma unroll
  for (int nb = 0; nb < 2; ++nb) {
    int col = wn + nb * 8 + 2 * q;
    gsm[(wm + g) * 65 + col]     = c[nb][0];
    gsm[(wm + g) * 65 + col + 1] = c[nb][1];
    gsm[(wm + g + 8) * 65 + col]     = c[nb][2];
    gsm[(wm + g + 8) * 65 + col + 1] = c[nb][3];
  }
  __syncthreads();

  float* hbuf = (float*)sm + 2112;  // 32 x 17
  int hbase = by * 16;
#pragma unroll
  for (int uu = 0; uu < 2; ++uu) {
    int e = tid + uu * 256;
    int r = e >> 4, hid = e & 15;
    int gb = row0 + r, gh = hbase + hid;
    float gi = gsm[r * 65 + hid]      + bias[0 * HSZ + gh];
    float gf = gsm[r * 65 + 16 + hid] + bias[1 * HSZ + gh];
    float gg = gsm[r * 65 + 32 + hid] + bias[2 * HSZ + gh];
    float go = gsm[r * 65 + 48 + hid] + bias[3 * HSZ + gh];
    float cold = c_state[gb * HSZ + gh];
    float si = 1.f / (1.f + expf(-gi));
    float sf = 1.f / (1.f + expf(-gf));
    float so = 1.f / (1.f + expf(-go));
    float cn = sf * cold + si * tanhf(gg);
    float hn = so * tanhf(cn);
    c_state[gb * HSZ + gh] = cn;
    hbuf[r * 17 + hid] = hn;
    if (outF) outF[gb * HSZ + gh] = hn;
  }
  __syncthreads();

  // ---- pack h -> bf16 hi/lo words (swizzled pair layout) ----
  {
    int row = tid >> 3, jj = tid & 7;
    int lp = j2lp(jj);
    float v0 = hbuf[row * 17 + 2 * lp];
    float v1 = hbuf[row * 17 + 2 * lp + 1];
    uint32_t hi, lo;
    split2(v0, v1, hi, lo);
    size_t oidx = (size_t)(row0 + row) * PH + by * 8 + jj;
    outHi[oidx] = hi;
    outLo[oidx] = lo;
  }
}

// ---------------- final projection over all decoder steps ----------------
__global__ __launch_bounds__(256) void out_proj(const float* __restrict__ Wout,
                                                const float* __restrict__ bout,
                                                float* __restrict__ out) {
  __shared__ float hs[32][65];
  __shared__ float wsT[64][36];
  int tid = threadIdx.x;
  int b0 = blockIdx.x * 32;
  int s = blockIdx.y;
  int bloc = tid & 31;
  int f0 = (tid >> 5) * 4;
  float acc[4] = {0.f, 0.f, 0.f, 0.f};
  const float* hsrc = g_h1s + (size_t)s * BSZ * HSZ;

  for (int k0 = 0; k0 < HSZ; k0 += 64) {
    __syncthreads();
#pragma unroll
    for (int qq = 0; qq < 2; ++qq) {
      int idx = tid + qq * 256;
      int row = idx >> 4, kq = idx & 15;
      float4 v = *(const float4*)(hsrc + (size_t)(b0 + row) * HSZ + k0 + kq * 4);
      hs[row][kq * 4 + 0] = v.x; hs[row][kq * 4 + 1] = v.y;
      hs[row][kq * 4 + 2] = v.z; hs[row][kq * 4 + 3] = v.w;
      float4 w = *(const float4*)(Wout + (size_t)row * HSZ + k0 + kq * 4);
      wsT[kq * 4 + 0][row] = w.x; wsT[kq * 4 + 1][row] = w.y;
      wsT[kq * 4 + 2][row] = w.z; wsT[kq * 4 + 3][row] = w.w;
    }
    __syncthreads();
#pragma unroll 8
    for (int kk = 0; kk < 64; ++kk) {
      float hv = hs[bloc][kk];
      float4 w = *(const float4*)&wsT[kk][f0];
      acc[0] += hv * w.x; acc[1] += hv * w.y;
      acc[2] += hv * w.z; acc[3] += hv * w.w;
    }
  }
  float* op = out + (size_t)(b0 + bloc) * TOUT * FSZ + s * FSZ + f0;
  op[0] = acc[0] + bout[f0 + 0];
  op[1] = acc[1] + bout[f0 + 1];
  op[2] = acc[2] + bout[f0 + 2];
  op[3] = acc[3] + bout[f0 + 3];
}

// ---------------- host ----------------
template <typename T>
static T* sym_addr(const void* sym) {
  void* p = nullptr;
  cudaGetSymbolAddress(&p, sym);
  return (T*)p;
}

extern "C" void kernel_launch(void* const* d_in, const int* in_sizes, int n_in,
                              void* d_out, int out_size) {
  (void)in_sizes; (void)n_in; (void)out_size;
  const float* x     = (const float*)d_in[0];
  const float* eWih0 = (const float*)d_in[1];
  const float* eWhh0 = (const float*)d_in[2];
  const float* eb0   = (const float*)d_in[3];
  const float* eWih1 = (const float*)d_in[4];
  const float* eWhh1 = (const float*)d_in[5];
  const float* eb1   = (const float*)d_in[6];
  const float* dWih0 = (const float*)d_in[7];
  const float* dWhh0 = (const float*)d_in[8];
  const float* db0   = (const float*)d_in[9];
  const float* dWih1 = (const float*)d_in[10];
  const float* dWhh1 = (const float*)d_in[11];
  const float* db1   = (const float*)d_in[12];
  const float* dWout = (const float*)d_in[13];
  const float* dbout = (const float*)d_in[14];

  uint32_t* h0hi = sym_addr<uint32_t>(g_h0hi);
  uint32_t* h0lo = sym_addr<uint32_t>(g_h0lo);
  uint32_t* h1hi = sym_addr<uint32_t>(g_h1hi);
  uint32_t* h1lo = sym_addr<uint32_t>(g_h1lo);
  float* c0 = sym_addr<float>(g_c0);
  float* c1 = sym_addr<float>(g_c1);
  uint32_t* xhi = sym_addr<uint32_t>(g_xhi);
  uint32_t* xlo = sym_addr<uint32_t>(g_xlo);
  float* Wp = sym_addr<float>(g_Wp);
  float* bp = sym_addr<float>(g_bp);
  float* h1s = sym_addr<float>(g_h1s);

  uint32_t* eWih0h = sym_addr<uint32_t>(g_eWih0h); uint32_t* eWih0l = sym_addr<uint32_t>(g_eWih0l);
  uint32_t* eWhh0h = sym_addr<uint32_t>(g_eWhh0h); uint32_t* eWhh0l = sym_addr<uint32_t>(g_eWhh0l);
  uint32_t* eWih1h = sym_addr<uint32_t>(g_eWih1h); uint32_t* eWih1l = sym_addr<uint32_t>(g_eWih1l);
  uint32_t* eWhh1h = sym_addr<uint32_t>(g_eWhh1h); uint32_t* eWhh1l = sym_addr<uint32_t>(g_eWhh1l);
  uint32_t* dWih0h = sym_addr<uint32_t>(g_dWih0h); uint32_t* dWih0l = sym_addr<uint32_t>(g_dWih0l);
  uint32_t* dWhh0h = sym_addr<uint32_t>(g_dWhh0h); uint32_t* dWhh0l = sym_addr<uint32_t>(g_dWhh0l);
  uint32_t* dWih1h = sym_addr<uint32_t>(g_dWih1h); uint32_t* dWih1l = sym_addr<uint32_t>(g_dWih1l);
  uint32_t* dWhh1h = sym_addr<uint32_t>(g_dWhh1h); uint32_t* dWhh1l = sym_addr<uint32_t>(g_dWhh1l);
  uint32_t* Wph = sym_addr<uint32_t>(g_Wph);       uint32_t* Wpl = sym_addr<uint32_t>(g_Wpl);

  const int pW = BSZ * PH;          // packed words per h buffer
  const int pN = BSZ * HSZ;
  const int ldx = TIN * PX;
  dim3 grid(BSZ / 32, HSZ / 16);

  zero_init_kernel<<<(BSZ * HSZ) / 256, 256>>>();
  wp_kernel<<<4 * HSZ, 256>>>(dWih0, dWout);
  bp_kernel<<<(4 * HSZ) / 256, 256>>>(dWih0, db0, dbout);
  pack_x<<<(BSZ * TIN * PX) / 256, 256>>>(x);
  pack_w<<<(1024 * 16) / 256, 256>>>(eWih0, 32, eWih0h, eWih0l);
  pack_w<<<(1024 * 128) / 256, 256>>>(eWhh0, 256, eWhh0h, eWhh0l);
  pack_w<<<(1024 * 128) / 256, 256>>>(eWih1, 256, eWih1h, eWih1l);
  pack_w<<<(1024 * 128) / 256, 256>>>(eWhh1, 256, eWhh1h, eWhh1l);
  pack_w<<<(1024 * 16) / 256, 256>>>(dWih0, 32, dWih0h, dWih0l);
  pack_w<<<(1024 * 128) / 256, 256>>>(dWhh0, 256, dWhh0h, dWhh0l);
  pack_w<<<(1024 * 128) / 256, 256>>>(dWih1, 256, dWih1h, dWih1l);
  pack_w<<<(1024 * 128) / 256, 256>>>(dWhh1, 256, dWhh1h, dWhh1l);
  pack_w<<<(1024 * 128) / 256, 256>>>(Wp, 256, Wph, Wpl);

  int par = 0;
  // -------- encoder --------
  for (int t = 0; t < TIN; ++t) {
    lstm_step<<<grid, 256>>>(xhi + (size_t)t * PX, xlo + (size_t)t * PX,
                             ldx, PX, eWih0h, eWih0l,
                             h0hi + par * pW, h0lo + par * pW,
                             eWhh0h, eWhh0l, eb0, c0,
                             h0hi + (par ^ 1) * pW, h0lo + (par ^ 1) * pW,
                             nullptr);
    lstm_step<<<grid, 256>>>(h0hi + (par ^ 1) * pW, h0lo + (par ^ 1) * pW,
                             PH, PH, eWih1h, eWih1l,
                             h1hi + par * pW, h1lo + par * pW,
                             eWhh1h, eWhh1l, eb1, c1,
                             h1hi + (par ^ 1) * pW, h1lo + (par ^ 1) * pW,
                             nullptr);
    par ^= 1;
  }
  // -------- decoder --------
  for (int s = 0; s < TOUT; ++s) {
    if (s == 0) {
      lstm_step<<<grid, 256>>>(xhi + (size_t)(TIN - 1) * PX,
                               xlo + (size_t)(TIN - 1) * PX,
                               ldx, PX, dWih0h, dWih0l,
                               h0hi + par * pW, h0lo + par * pW,
                               dWhh0h, dWhh0l, db0, c0,
                               h0hi + (par ^ 1) * pW, h0lo + (par ^ 1) * pW,
                               nullptr);
    } else {
      // y-feedback folded: W' = dec_Wih0 @ dec_Wout, b' = dec_b0 + dec_Wih0 @ dec_bout
      lstm_step<<<grid, 256>>>(h1hi + par * pW, h1lo + par * pW,
                               PH, PH, Wph, Wpl,
                               h0hi + par * pW, h0lo + par * pW,
                               dWhh0h, dWhh0l, bp, c0,
                               h0hi + (par ^ 1) * pW, h0lo + (par ^ 1) * pW,
                               nullptr);
    }
    lstm_step<<<grid, 256>>>(h0hi + (par ^ 1) * pW, h0lo + (par ^ 1) * pW,
                             PH, PH, dWih1h, dWih1l,
                             h1hi + par * pW, h1lo + par * pW,
                             dWhh1h, dWhh1l, db1, c1,
                             h1hi + (par ^ 1) * pW, h1lo + (par ^ 1) * pW,
                             h1s + (size_t)s * pN);
    par ^= 1;
  }
  // -------- output projection --------
  out_proj<<<dim3(BSZ / 32, TOUT), 256>>>(dWout, dbout, (float*)d_out);
}

// round 11
// speedup vs baseline: 1.5245x; 1.5245x over previous
#include <cuda_runtime.h>
#include <cuda_bf16.h>
#include <math.h>
#include <stdint.h>

#define BSZ 256
#define HSZ 256
#define TIN 336
#define TOUT 96
#define FSZ 32
#define PH 128
#define PX 16
#define NCTA 128
#define SMW 57344  // dynamic smem words (229376 bytes)

__device__ uint32_t g_h0hi[2][BSZ * PH], g_h0lo[2][BSZ * PH];
__device__ uint32_t g_h1hi[2][BSZ * PH], g_h1lo[2][BSZ * PH];
__device__ uint32_t g_xhi[BSZ * TIN * PX], g_xlo[BSZ * TIN * PX];
__device__ float g_Wp[4 * HSZ * HSZ], g_bp[4 * HSZ];
__device__ float g_h1s[(size_t)TOUT * BSZ * HSZ];
__device__ unsigned g_bar;

__device__ uint32_t g_eWih0h[1024 * 16],  g_eWih0l[1024 * 16];
__device__ uint32_t g_eWhh0h[1024 * 128], g_eWhh0l[1024 * 128];
__device__ uint32_t g_eWih1h[1024 * 128], g_eWih1l[1024 * 128];
__device__ uint32_t g_eWhh1h[1024 * 128], g_eWhh1l[1024 * 128];
__device__ uint32_t g_dWih0h[1024 * 16],  g_dWih0l[1024 * 16];
__device__ uint32_t g_dWhh0h[1024 * 128], g_dWhh0l[1024 * 128];
__device__ uint32_t g_dWih1h[1024 * 128], g_dWih1l[1024 * 128];
__device__ uint32_t g_dWhh1h[1024 * 128], g_dWhh1l[1024 * 128];
__device__ uint32_t g_Wph[1024 * 128],    g_Wpl[1024 * 128];

__device__ __forceinline__ int j2lp(int j) { return ((j & 1) << 2) | (j >> 1); }

__device__ __forceinline__ void split2(float v0, float v1, uint32_t& hi, uint32_t& lo) {
  __nv_bfloat16 h0 = __float2bfloat16_rn(v0), h1 = __float2bfloat16_rn(v1);
  __nv_bfloat16 l0 = __float2bfloat16_rn(v0 - __bfloat162float(h0));
  __nv_bfloat16 l1 = __float2bfloat16_rn(v1 - __bfloat162float(h1));
  __nv_bfloat162 ph = __nv_bfloat162(h0, h1), pl = __nv_bfloat162(l0, l1);
  hi = *(uint32_t*)&ph;
  lo = *(uint32_t*)&pl;
}

#define MMA_BF16(C, a0, a1, a2, a3, b0, b1)                                   \
  asm volatile(                                                               \
      "mma.sync.aligned.m16n8k16.row.col.f32.bf16.bf16.f32 "                  \
      "{%0,%1,%2,%3},{%4,%5,%6,%7},{%8,%9},{%0,%1,%2,%3};"                    \
      : "+f"(C[0]), "+f"(C[1]), "+f"(C[2]), "+f"(C[3])                        \
      : "r"(a0), "r"(a1), "r"(a2), "r"(a3), "r"(b0), "r"(b1))

#define LDG_CG2(v, p)                                                         \
  asm volatile("ld.global.cg.v2.u32 {%0,%1},[%2];"                            \
               : "=r"((v).x), "=r"((v).y) : "l"(p))

// ---------------- init / preprocess ----------------
__global__ void zero_init_kernel() {
  int i = blockIdx.x * blockDim.x + threadIdx.x;  // 32768
  g_h0hi[0][i] = 0u; g_h0lo[0][i] = 0u;
  g_h1hi[0][i] = 0u; g_h1lo[0][i] = 0u;
  if (i == 0) g_bar = 0u;
}

__global__ void wp_kernel(const float* __restrict__ Wih0, const float* __restrict__ Wout) {
  __shared__ float wr[FSZ];
  int c = blockIdx.x;
  if (threadIdx.x < FSZ) wr[threadIdx.x] = Wih0[c * FSZ + threadIdx.x];
  __syncthreads();
  int k = threadIdx.x;
  float acc = 0.f;
#pragma unroll
  for (int f = 0; f < FSZ; ++f) acc += wr[f] * Wout[f * HSZ + k];
  g_Wp[c * HSZ + k] = acc;
}

__global__ void bp_kernel(const float* __restrict__ Wih0, const float* __restrict__ b0,
                          const float* __restrict__ bout) {
  int c = blockIdx.x * blockDim.x + threadIdx.x;
  float acc = b0[c];
#pragma unroll
  for (int f = 0; f < FSZ; ++f) acc += Wih0[c * FSZ + f] * bout[f];
  g_bp[c] = acc;
}

__global__ void pack_w(const float* __restrict__ W, int K,
                       uint32_t* __restrict__ ohi, uint32_t* __restrict__ olo) {
  int P = K >> 1;
  int idx = blockIdx.x * 256 + threadIdx.x;
  if (idx >= 1024 * P) return;
  int pr = idx / P, w = idx % P;
  int n = pr & 63, by = pr >> 6;
  int r = (n >> 4) * 256 + by * 16 + (n & 15);
  int cch = w >> 3, j = w & 7;
  int k0 = cch * 16 + 2 * j2lp(j);
  split2(W[r * K + k0], W[r * K + k0 + 1], ohi[idx], olo[idx]);
}

__global__ void pack_x(const float* __restrict__ x) {
  int idx = blockIdx.x * 256 + threadIdx.x;
  int w = idx & (PX - 1), bt = idx >> 4;
  int cch = w >> 3, j = w & 7;
  int k0 = cch * 16 + 2 * j2lp(j);
  const float* src = x + (size_t)bt * FSZ + k0;
  split2(src[0], src[1], g_xhi[idx], g_xlo[idx]);
}

// ---------------- persistent building blocks ----------------
__device__ __forceinline__ void gbar(unsigned target) {
  __syncthreads();
  __threadfence();
  if (threadIdx.x == 0) {
    atomicAdd(&g_bar, 1u);
    volatile unsigned* p = &g_bar;
    while (*p < target) {}
  }
  __syncthreads();
}

// load 64-row weight slice into SMEM, chunk-major 512-word blocks
__device__ __forceinline__ void ld_res(uint32_t* dst, const uint32_t* src,
                                       int P, int by, int tid) {
  const uint32_t* s = src + (size_t)(by * 64) * P;
  for (int idx = tid * 2; idx < 64 * P; idx += 512) {
    int rw = idx / P, w = idx - rw * P;
    int c = w >> 3, j = w & 7;
    uint2 v = *(const uint2*)(s + (size_t)rw * P + w);
    *(uint2*)&dst[c * 512 + rw * 8 + j] = v;
  }
}

template <int NCH>
__device__ __forceinline__ void seg_mma(
    float* acc0, float* acc1,
    const uint32_t* __restrict__ Ahi, const uint32_t* __restrict__ Alo,
    int ldA, bool cg,
    const uint32_t* __restrict__ sWhi, const uint32_t* __restrict__ sWlo,
    const uint32_t* __restrict__ gWlo,
    uint32_t* __restrict__ sA, uint32_t* __restrict__ sWst,
    int tid, int row0, int aoff, int boff0, int boff1) {
#pragma unroll
  for (int g0 = 0; g0 < NCH; g0 += 8) {
    const int gc = (NCH - g0 < 8) ? (NCH - g0) : 8;
    __syncthreads();
    for (int idx = tid * 2; idx < gc * 256; idx += 512) {
      int c = idx >> 8, rem = idx & 255, rw = rem >> 3, j = rem & 7;
      size_t go = (size_t)(row0 + rw) * ldA + ((g0 + c) << 3) + j;
      uint2 vh, vl;
      if (cg) { LDG_CG2(vh, Ahi + go); LDG_CG2(vl, Alo + go); }
      else { vh = *(const uint2*)(Ahi + go); vl = *(const uint2*)(Alo + go); }
      *(uint2*)&sA[idx] = vh;
      *(uint2*)&sA[2048 + idx] = vl;
    }
    if (gWlo) {
      for (int idx = tid * 2; idx < gc * 512; idx += 512) {
        int c = idx >> 9, rem = idx & 511, rw = rem >> 3, j = rem & 7;
        uint2 v;
        LDG_CG2(v, gWlo + (size_t)rw * (NCH * 8) + ((g0 + c) << 3) + j);
        *(uint2*)&sWst[idx] = v;
      }
    }
    __syncthreads();
#pragma unroll
    for (int c = 0; c < gc; ++c) {
      const uint32_t* bAh = sA + (c << 8);
      const uint32_t* bAl = bAh + 2048;
      const uint32_t* bWh = sWhi + ((g0 + c) << 9);
      const uint32_t* bWl = gWlo ? (sWst + (c << 9)) : (sWlo + ((g0 + c) << 9));
      uint2 Ah0 = *(const uint2*)(bAh + aoff), Ah1 = *(const uint2*)(bAh + aoff + 64);
      uint2 Al0 = *(const uint2*)(bAl + aoff), Al1 = *(const uint2*)(bAl + aoff + 64);
      uint2 Bh0 = *(const uint2*)(bWh + boff0), Bl0 = *(const uint2*)(bWl + boff0);
      uint2 Bh1 = *(const uint2*)(bWh + boff1), Bl1 = *(const uint2*)(bWl + boff1);
      MMA_BF16(acc0, Ah0.x, Ah1.x, Ah0.y, Ah1.y, Bh0.x, Bh0.y);
      MMA_BF16(acc0, Ah0.x, Ah1.x, Ah0.y, Ah1.y, Bl0.x, Bl0.y);
      MMA_BF16(acc0, Al0.x, Al1.x, Al0.y, Al1.y, Bh0.x, Bh0.y);
      MMA_BF16(acc1, Ah0.x, Ah1.x, Ah0.y, Ah1.y, Bh1.x, Bh1.y);
      MMA_BF16(acc1, Ah0.x, Ah1.x, Ah0.y, Ah1.y, Bl1.x, Bl1.y);
      MMA_BF16(acc1, Al0.x, Al1.x, Al0.y, Al1.y, Bh1.x, Bh1.y);
    }
  }
}

__device__ __forceinline__ void epilogue(
    const float* a0, const float* a1, float* creg, float4 bu,
    int row0, int by, int tid, int wm, int wn, int g, int q,
    uint32_t* __restrict__ outHi, uint32_t* __restrict__ outLo,
    float* __restrict__ outF, float* gsm) {
  __syncthreads();
  int col0 = wn + 2 * q, col1 = wn + 8 + 2 * q;
  gsm[(wm + g) * 65 + col0] = a0[0];     gsm[(wm + g) * 65 + col0 + 1] = a0[1];
  gsm[(wm + g + 8) * 65 + col0] = a0[2]; gsm[(wm + g + 8) * 65 + col0 + 1] = a0[3];
  gsm[(wm + g) * 65 + col1] = a1[0];     gsm[(wm + g) * 65 + col1 + 1] = a1[1];
  gsm[(wm + g + 8) * 65 + col1] = a1[2]; gsm[(wm + g + 8) * 65 + col1 + 1] = a1[3];
  __syncthreads();
  float* hbuf = gsm + 2112;
#pragma unroll
  for (int uu = 0; uu < 2; ++uu) {
    int e = tid + uu * 256, r = e >> 4, hid = e & 15;
    float gi = gsm[r * 65 + hid] + bu.x;
    float gf = gsm[r * 65 + 16 + hid] + bu.y;
    float gg = gsm[r * 65 + 32 + hid] + bu.z;
    float go = gsm[r * 65 + 48 + hid] + bu.w;
    float si = 1.f / (1.f + expf(-gi));
    float sf = 1.f / (1.f + expf(-gf));
    float so = 1.f / (1.f + expf(-go));
    float cn = sf * creg[uu] + si * tanhf(gg);
    float hn = so * tanhf(cn);
    creg[uu] = cn;
    hbuf[r * 17 + hid] = hn;
    if (outF) outF[(size_t)(row0 + r) * HSZ + by * 16 + hid] = hn;
  }
  __syncthreads();
  int pr = tid >> 3, jj = tid & 7, lp = j2lp(jj);
  uint32_t hi, lo;
  split2(hbuf[pr * 17 + 2 * lp], hbuf[pr * 17 + 2 * lp + 1], hi, lo);
  size_t o = (size_t)(row0 + pr) * PH + by * 8 + jj;
  outHi[o] = hi;
  outLo[o] = lo;
}

__device__ __forceinline__ float4 bias4(const float* b, int gh) {
  return make_float4(b[gh], b[HSZ + gh], b[2 * HSZ + gh], b[3 * HSZ + gh]);
}

// ---------------- persistent kernel: all 432 steps ----------------
__global__ __launch_bounds__(256) void lstm_persist(
    const float* __restrict__ eb0, const float* __restrict__ eb1,
    const float* __restrict__ db0, const float* __restrict__ db1) {
  extern __shared__ uint32_t smem[];
  int tid = threadIdx.x;
  int bx = blockIdx.x & 7, by = blockIdx.x >> 3;
  int row0 = bx * 32;
  int lane = tid & 31, wid = tid >> 5, g = lane >> 2, q = lane & 3;
  int wm = (wid & 1) * 16, wn = (wid >> 1) * 16;
  int aoff = (wm + g) * 8 + 2 * q;
  int boff0 = (wn + g) * 8 + 2 * q, boff1 = (wn + 8 + g) * 8 + 2 * q;
  uint32_t* sA = smem + 49152;
  uint32_t* sWst = smem + 53248;
  float* gsm = (float*)sA;
  int gh = by * 16 + (tid & 15);
  float c0r[2] = {0.f, 0.f}, c1r[2] = {0.f, 0.f};
  unsigned bt = 0;
  int par = 0;

  // ---- encoder phase ----
  ld_res(smem + 0,     g_eWhh0h, 128, by, tid);
  ld_res(smem + 8192,  g_eWhh0l, 128, by, tid);
  ld_res(smem + 16384, g_eWih1h, 128, by, tid);
  ld_res(smem + 24576, g_eWih1l, 128, by, tid);
  ld_res(smem + 32768, g_eWhh1h, 128, by, tid);
  ld_res(smem + 40960, g_eWhh1l, 128, by, tid);
  ld_res(sWst,         g_eWih0h, 16, by, tid);
  ld_res(sWst + 1024,  g_eWih0l, 16, by, tid);
  float4 be0 = bias4(eb0, gh), be1 = bias4(eb1, gh);

  for (int t = 0; t < TIN; ++t) {
    float a0[4] = {}, a1[4] = {};
    seg_mma<2>(a0, a1, g_xhi + (size_t)t * PX, g_xlo + (size_t)t * PX,
               TIN * PX, false, sWst, sWst + 1024, nullptr, sA, nullptr,
               tid, row0, aoff, boff0, boff1);
    seg_mma<16>(a0, a1, g_h0hi[par], g_h0lo[par], PH, true,
                smem + 0, smem + 8192, nullptr, sA, nullptr,
                tid, row0, aoff, boff0, boff1);
    epilogue(a0, a1, c0r, be0, row0, by, tid, wm, wn, g, q,
             g_h0hi[par ^ 1], g_h0lo[par ^ 1], nullptr, gsm);
    bt += NCTA; gbar(bt);

    float d0[4] = {}, d1[4] = {};
    seg_mma<16>(d0, d1, g_h0hi[par ^ 1], g_h0lo[par ^ 1], PH, true,
                smem + 16384, smem + 24576, nullptr, sA, nullptr,
                tid, row0, aoff, boff0, boff1);
    seg_mma<16>(d0, d1, g_h1hi[par], g_h1lo[par], PH, true,
                smem + 32768, smem + 40960, nullptr, sA, nullptr,
                tid, row0, aoff, boff0, boff1);
    epilogue(d0, d1, c1r, be1, row0, by, tid, wm, wn, g, q,
             g_h1hi[par ^ 1], g_h1lo[par ^ 1], nullptr, gsm);
    bt += NCTA; gbar(bt);
    par ^= 1;
  }

  // ---- decoder phase: reload resident weights ----
  ld_res(smem + 0,     g_Wph,    128, by, tid);
  ld_res(smem + 8192,  g_Wpl,    128, by, tid);
  ld_res(smem + 16384, g_dWhh0h, 128, by, tid);
  ld_res(smem + 24576, g_dWhh0l, 128, by, tid);
  ld_res(smem + 32768, g_dWih1h, 128, by, tid);
  ld_res(smem + 40960, g_dWhh1h, 128, by, tid);
  ld_res(sWst,         g_dWih0h, 16, by, tid);
  ld_res(sWst + 1024,  g_dWih0l, 16, by, tid);
  __syncthreads();
  const uint32_t* ih1lo = g_dWih1l + (size_t)by * 64 * PH;
  const uint32_t* hh1lo = g_dWhh1l + (size_t)by * 64 * PH;
  float4 bd0 = bias4(db0, gh), bdp = bias4(g_bp, gh), bd1 = bias4(db1, gh);

  for (int s = 0; s < TOUT; ++s) {
    float a0[4] = {}, a1[4] = {};
    if (s == 0) {
      seg_mma<2>(a0, a1, g_xhi + (size_t)(TIN - 1) * PX,
                 g_xlo + (size_t)(TIN - 1) * PX, TIN * PX, false,
                 sWst, sWst + 1024, nullptr, sA, nullptr,
                 tid, row0, aoff, boff0, boff1);
    } else {
      seg_mma<16>(a0, a1, g_h1hi[par], g_h1lo[par], PH, true,
                  smem + 0, smem + 8192, nullptr, sA, nullptr,
                  tid, row0, aoff, boff0, boff1);
    }
    seg_mma<16>(a0, a1, g_h0hi[par], g_h0lo[par], PH, true,
                smem + 16384, smem + 24576, nullptr, sA, nullptr,
                tid, row0, aoff, boff0, boff1);
    epilogue(a0, a1, c0r, s ? bdp : bd0, row0, by, tid, wm, wn, g, q,
             g_h0hi[par ^ 1], g_h0lo[par ^ 1], nullptr, gsm);
    bt += NCTA; gbar(bt);

    float d0[4] = {}, d1[4] = {};
    seg_mma<16>(d0, d1, g_h0hi[par ^ 1], g_h0lo[par ^ 1], PH, true,
                smem + 32768, nullptr, ih1lo, sA, sWst,
                tid, row0, aoff, boff0, boff1);
    seg_mma<16>(d0, d1, g_h1hi[par], g_h1lo[par], PH, true,
                smem + 40960, nullptr, hh1lo, sA, sWst,
                tid, row0, aoff, boff0, boff1);
    epilogue(d0, d1, c1r, bd1, row0, by, tid, wm, wn, g, q,
             g_h1hi[par ^ 1], g_h1lo[par ^ 1],
             g_h1s + (size_t)s * BSZ * HSZ, gsm);
    bt += NCTA; gbar(bt);
    par ^= 1;
  }
}

// ---------------- final projection ----------------
__global__ __launch_bounds__(256) void out_proj(const float* __restrict__ Wout,
                                                const float* __restrict__ bout,
                                                float* __restrict__ out) {
  __shared__ float hs[32][65];
  __shared__ float wsT[64][36];
  int tid = threadIdx.x;
  int b0 = blockIdx.x * 32, s = blockIdx.y;
  int bloc = tid & 31, f0 = (tid >> 5) * 4;
  float acc[4] = {0.f, 0.f, 0.f, 0.f};
  const float* hsrc = g_h1s + (size_t)s * BSZ * HSZ;
  for (int k0 = 0; k0 < HSZ; k0 += 64) {
    __syncthreads();
#pragma unroll
    for (int qq = 0; qq < 2; ++qq) {
      int idx = tid + qq * 256, row = idx >> 4, kq = idx & 15;
      float4 v = *(const float4*)(hsrc + (size_t)(b0 + row) * HSZ + k0 + kq * 4);
      hs[row][kq * 4 + 0] = v.x; hs[row][kq * 4 + 1] = v.y;
      hs[row][kq * 4 + 2] = v.z; hs[row][kq * 4 + 3] = v.w;
      float4 w = *(const float4*)(Wout + (size_t)row * HSZ + k0 + kq * 4);
      wsT[kq * 4 + 0][row] = w.x; wsT[kq * 4 + 1][row] = w.y;
      wsT[kq * 4 + 2][row] = w.z; wsT[kq * 4 + 3][row] = w.w;
    }
    __syncthreads();
#pragma unroll 8
    for (int kk = 0; kk < 64; ++kk) {
      float hv = hs[bloc][kk];
      float4 w = *(const float4*)&wsT[kk][f0];
      acc[0] += hv * w.x; acc[1] += hv * w.y;
      acc[2] += hv * w.z; acc[3] += hv * w.w;
    }
  }
  float* op = out + (size_t)(b0 + bloc) * TOUT * FSZ + s * FSZ + f0;
  op[0] = acc[0] + bout[f0 + 0];
  op[1] = acc[1] + bout[f0 + 1];
  op[2] = acc[2] + bout[f0 + 2];
  op[3] = acc[3] + bout[f0 + 3];
}

// ---------------- host ----------------
extern "C" void kernel_launch(void* const* d_in, const int* in_sizes, int n_in,
                              void* d_out, int out_size) {
  (void)in_sizes; (void)n_in; (void)out_size;
  const float* x     = (const float*)d_in[0];
  const float* eWih0 = (const float*)d_in[1];
  const float* eWhh0 = (const float*)d_in[2];
  const float* eb0   = (const float*)d_in[3];
  const float* eWih1 = (const float*)d_in[4];
  const float* eWhh1 = (const float*)d_in[5];
  const float* eb1   = (const float*)d_in[6];
  const float* dWih0 = (const float*)d_in[7];
  const float* dWhh0 = (const float*)d_in[8];
  const float* db0   = (const float*)d_in[9];
  const float* dWih1 = (const float*)d_in[10];
  const float* dWhh1 = (const float*)d_in[11];
  const float* db1   = (const float*)d_in[12];
  const float* dWout = (const float*)d_in[13];
  const float* dbout = (const float*)d_in[14];

  void* p;
  cudaGetSymbolAddress(&p, g_Wp);      float* Wp = (float*)p;
  cudaGetSymbolAddress(&p, g_eWih0h);  uint32_t* eWih0h = (uint32_t*)p;
  cudaGetSymbolAddress(&p, g_eWih0l);  uint32_t* eWih0l = (uint32_t*)p;
  cudaGetSymbolAddress(&p, g_eWhh0h);  uint32_t* eWhh0h = (uint32_t*)p;
  cudaGetSymbolAddress(&p, g_eWhh0l);  uint32_t* eWhh0l = (uint32_t*)p;
  cudaGetSymbolAddress(&p, g_eWih1h);  uint32_t* eWih1h = (uint32_t*)p;
  cudaGetSymbolAddress(&p, g_eWih1l);  uint32_t* eWih1l = (uint32_t*)p;
  cudaGetSymbolAddress(&p, g_eWhh1h);  uint32_t* eWhh1h = (uint32_t*)p;
  cudaGetSymbolAddress(&p, g_eWhh1l);  uint32_t* eWhh1l = (uint32_t*)p;
  cudaGetSymbolAddress(&p, g_dWih0h);  uint32_t* dWih0h = (uint32_t*)p;
  cudaGetSymbolAddress(&p, g_dWih0l);  uint32_t* dWih0l = (uint32_t*)p;
  cudaGetSymbolAddress(&p, g_dWhh0h);  uint32_t* dWhh0h = (uint32_t*)p;
  cudaGetSymbolAddress(&p, g_dWhh0l);  uint32_t* dWhh0l = (uint32_t*)p;
  cudaGetSymbolAddress(&p, g_dWih1h);  uint32_t* dWih1h = (uint32_t*)p;
  cudaGetSymbolAddress(&p, g_dWih1l);  uint32_t* dWih1l = (uint32_t*)p;
  cudaGetSymbolAddress(&p, g_dWhh1h);  uint32_t* dWhh1h = (uint32_t*)p;
  cudaGetSymbolAddress(&p, g_dWhh1l);  uint32_t* dWhh1l = (uint32_t*)p;
  cudaGetSymbolAddress(&p, g_Wph);     uint32_t* Wph = (uint32_t*)p;
  cudaGetSymbolAddress(&p, g_Wpl);     uint32_t* Wpl = (uint32_t*)p;

  cudaFuncSetAttribute(lstm_persist, cudaFuncAttributeMaxDynamicSharedMemorySize,
                       SMW * 4);

  zero_init_kernel<<<(BSZ * PH) / 256, 256>>>();
  wp_kernel<<<4 * HSZ, 256>>>(dWih0, dWout);
  bp_kernel<<<(4 * HSZ) / 256, 256>>>(dWih0, db0, dbout);
  pack_x<<<(BSZ * TIN * PX) / 256, 256>>>(x);
  pack_w<<<(1024 * 16) / 256, 256>>>(eWih0, 32, eWih0h, eWih0l);
  pack_w<<<(1024 * 128) / 256, 256>>>(eWhh0, 256, eWhh0h, eWhh0l);
  pack_w<<<(1024 * 128) / 256, 256>>>(eWih1, 256, eWih1h, eWih1l);
  pack_w<<<(1024 * 128) / 256, 256>>>(eWhh1, 256, eWhh1h, eWhh1l);
  pack_w<<<(1024 * 16) / 256, 256>>>(dWih0, 32, dWih0h, dWih0l);
  pack_w<<<(1024 * 128) / 256, 256>>>(dWhh0, 256, dWhh0h, dWhh0l);
  pack_w<<<(1024 * 128) / 256, 256>>>(dWih1, 256, dWih1h, dWih1l);
  pack_w<<<(1024 * 128) / 256, 256>>>(dWhh1, 256, dWhh1h, dWhh1l);
  pack_w<<<(1024 * 128) / 256, 256>>>(Wp, 256, Wph, Wpl);

  lstm_persist<<<NCTA, 256, SMW * 4>>>(eb0, eb1, db0, db1);
  out_proj<<<dim3(BSZ / 32, TOUT), 256>>>(dWout, dbout, (float*)d_out);
}

// round 12
// speedup vs baseline: 1.9135x; 1.2552x over previous
#include <cuda_runtime.h>
#include <cuda_bf16.h>
#include <math.h>
#include <stdint.h>

#define BSZ 256
#define HSZ 256
#define TIN 336
#define TOUT 96
#define FSZ 32
#define PH 128
#define PX 16
#define NCTA 128
#define SMW 57344  // dynamic smem words (229376 bytes)

__device__ uint32_t g_h0hi[2][BSZ * PH], g_h0lo[2][BSZ * PH];
__device__ uint32_t g_h1hi[2][BSZ * PH], g_h1lo[2][BSZ * PH];
__device__ uint32_t g_xhi[BSZ * TIN * PX], g_xlo[BSZ * TIN * PX];
__device__ float g_Wp[4 * HSZ * HSZ], g_bp[4 * HSZ];
__device__ float g_h1s[(size_t)TOUT * BSZ * HSZ];
__device__ unsigned g_bar;

__device__ uint32_t g_eWih0h[1024 * 16],  g_eWih0l[1024 * 16];
__device__ uint32_t g_eWhh0h[1024 * 128], g_eWhh0l[1024 * 128];
__device__ uint32_t g_eWih1h[1024 * 128], g_eWih1l[1024 * 128];
__device__ uint32_t g_eWhh1h[1024 * 128], g_eWhh1l[1024 * 128];
__device__ uint32_t g_dWih0h[1024 * 16],  g_dWih0l[1024 * 16];
__device__ uint32_t g_dWhh0h[1024 * 128], g_dWhh0l[1024 * 128];
__device__ uint32_t g_dWih1h[1024 * 128], g_dWih1l[1024 * 128];
__device__ uint32_t g_dWhh1h[1024 * 128], g_dWhh1l[1024 * 128];
__device__ uint32_t g_Wph[1024 * 128],    g_Wpl[1024 * 128];

__device__ __forceinline__ int j2lp(int j) { return ((j & 1) << 2) | (j >> 1); }

__device__ __forceinline__ void split2(float v0, float v1, uint32_t& hi, uint32_t& lo) {
  __nv_bfloat16 h0 = __float2bfloat16_rn(v0), h1 = __float2bfloat16_rn(v1);
  __nv_bfloat16 l0 = __float2bfloat16_rn(v0 - __bfloat162float(h0));
  __nv_bfloat16 l1 = __float2bfloat16_rn(v1 - __bfloat162float(h1));
  __nv_bfloat162 ph = __nv_bfloat162(h0, h1), pl = __nv_bfloat162(l0, l1);
  hi = *(uint32_t*)&ph;
  lo = *(uint32_t*)&pl;
}

#define MMA_BF16(C, a0, a1, a2, a3, b0, b1)                                   \
  asm volatile(                                                               \
      "mma.sync.aligned.m16n8k16.row.col.f32.bf16.bf16.f32 "                  \
      "{%0,%1,%2,%3},{%4,%5,%6,%7},{%8,%9},{%0,%1,%2,%3};"                    \
      : "+f"(C[0]), "+f"(C[1]), "+f"(C[2]), "+f"(C[3])                        \
      : "r"(a0), "r"(a1), "r"(a2), "r"(a3), "r"(b0), "r"(b1))

#define LDG_CG2(v, p)                                                         \
  asm volatile("ld.global.cg.v2.u32 {%0,%1},[%2];"                            \
               : "=r"((v).x), "=r"((v).y) : "l"(p))

// ---------------- init / preprocess ----------------
__global__ void zero_init_kernel() {
  int i = blockIdx.x * blockDim.x + threadIdx.x;  // 32768
  g_h0hi[0][i] = 0u; g_h0lo[0][i] = 0u;
  g_h1hi[0][i] = 0u; g_h1lo[0][i] = 0u;
  if (i == 0) g_bar = 0u;
}

__global__ void wp_kernel(const float* __restrict__ Wih0, const float* __restrict__ Wout) {
  __shared__ float wr[FSZ];
  int c = blockIdx.x;
  if (threadIdx.x < FSZ) wr[threadIdx.x] = Wih0[c * FSZ + threadIdx.x];
  __syncthreads();
  int k = threadIdx.x;
  float acc = 0.f;
#pragma unroll
  for (int f = 0; f < FSZ; ++f) acc += wr[f] * Wout[f * HSZ + k];
  g_Wp[c * HSZ + k] = acc;
}

__global__ void bp_kernel(const float* __restrict__ Wih0, const float* __restrict__ b0,
                          const float* __restrict__ bout) {
  int c = blockIdx.x * blockDim.x + threadIdx.x;
  float acc = b0[c];
#pragma unroll
  for (int f = 0; f < FSZ; ++f) acc += Wih0[c * FSZ + f] * bout[f];
  g_bp[c] = acc;
}

__global__ void pack_w(const float* __restrict__ W, int K,
                       uint32_t* __restrict__ ohi, uint32_t* __restrict__ olo) {
  int P = K >> 1;
  int idx = blockIdx.x * 256 + threadIdx.x;
  if (idx >= 1024 * P) return;
  int pr = idx / P, w = idx % P;
  int n = pr & 63, by = pr >> 6;
  int r = (n >> 4) * 256 + by * 16 + (n & 15);
  int cch = w >> 3, j = w & 7;
  int k0 = cch * 16 + 2 * j2lp(j);
  split2(W[r * K + k0], W[r * K + k0 + 1], ohi[idx], olo[idx]);
}

__global__ void pack_x(const float* __restrict__ x) {
  int idx = blockIdx.x * 256 + threadIdx.x;
  int w = idx & (PX - 1), bt = idx >> 4;
  int cch = w >> 3, j = w & 7;
  int k0 = cch * 16 + 2 * j2lp(j);
  const float* src = x + (size_t)bt * FSZ + k0;
  split2(src[0], src[1], g_xhi[idx], g_xlo[idx]);
}

// ---------------- persistent building blocks ----------------
__device__ __forceinline__ void gbar(unsigned target) {
  __syncthreads();
  __threadfence();
  if (threadIdx.x == 0) {
    atomicAdd(&g_bar, 1u);
    volatile unsigned* p = &g_bar;
    while (*p < target) {}
  }
  __syncthreads();
}

__device__ __forceinline__ void ld_res(uint32_t* dst, const uint32_t* src,
                                       int P, int by, int tid) {
  const uint32_t* s = src + (size_t)(by * 64) * P;
  for (int idx = tid * 2; idx < 64 * P; idx += 512) {
    int rw = idx / P, w = idx - rw * P;
    int c = w >> 3, j = w & 7;
    uint2 v = *(const uint2*)(s + (size_t)rw * P + w);
    *(uint2*)&dst[c * 512 + rw * 8 + j] = v;
  }
}

// prefetch one group's A (hi+lo) and optional streamed W-lo into registers
template <int GC, bool SW>
__device__ __forceinline__ void ld_grp(uint2* rA, uint2* rW,
    const uint32_t* __restrict__ ahi, const uint32_t* __restrict__ alo,
    int lda, const uint32_t* __restrict__ gwl, int row0, int tid) {
#pragma unroll
  for (int it = 0; it < GC / 2; ++it) {
    int idx = tid * 2 + it * 512;
    int rw = (idx & 255) >> 3, j = idx & 7, c = idx >> 8;
    size_t go = (size_t)(row0 + rw) * lda + (c << 3) + j;
    LDG_CG2(rA[2 * it], ahi + go);
    LDG_CG2(rA[2 * it + 1], alo + go);
  }
  if (SW) {
#pragma unroll
    for (int it = 0; it < GC; ++it) {
      int idx = tid * 2 + it * 512;
      int rw = (idx & 511) >> 3, j = idx & 7, c = idx >> 9;
      LDG_CG2(rW[it], gwl + rw * PH + (c << 3) + j);
    }
  }
}

template <int GC, bool SW>
__device__ __forceinline__ void st_grp(const uint2* rA, const uint2* rW,
                                       uint32_t* sA, uint32_t* sWst, int tid) {
#pragma unroll
  for (int it = 0; it < GC / 2; ++it) {
    int idx = tid * 2 + it * 512;
    *(uint2*)&sA[idx] = rA[2 * it];
    *(uint2*)&sA[2048 + idx] = rA[2 * it + 1];
  }
  if (SW) {
#pragma unroll
    for (int it = 0; it < GC; ++it)
      *(uint2*)&sWst[tid * 2 + it * 512] = rW[it];
  }
}

template <int GC>
__device__ __forceinline__ void comp_grp(float* a0, float* a1,
    const uint32_t* sA, const uint32_t* swh, const uint32_t* swl,
    int aoff, int boff0, int boff1) {
#pragma unroll
  for (int c = 0; c < GC; ++c) {
    const uint32_t* bAh = sA + (c << 8);
    const uint32_t* bAl = bAh + 2048;
    const uint32_t* bWh = swh + (c << 9);
    const uint32_t* bWl = swl + (c << 9);
    uint2 Ah0 = *(const uint2*)(bAh + aoff), Ah1 = *(const uint2*)(bAh + aoff + 64);
    uint2 Al0 = *(const uint2*)(bAl + aoff), Al1 = *(const uint2*)(bAl + aoff + 64);
    uint2 Bh0 = *(const uint2*)(bWh + boff0), Bl0 = *(const uint2*)(bWl + boff0);
    uint2 Bh1 = *(const uint2*)(bWh + boff1), Bl1 = *(const uint2*)(bWl + boff1);
    MMA_BF16(a0, Ah0.x, Ah1.x, Ah0.y, Ah1.y, Bh0.x, Bh0.y);
    MMA_BF16(a0, Ah0.x, Ah1.x, Ah0.y, Ah1.y, Bl0.x, Bl0.y);
    MMA_BF16(a0, Al0.x, Al1.x, Al0.y, Al1.y, Bh0.x, Bh0.y);
    MMA_BF16(a1, Ah0.x, Ah1.x, Ah0.y, Ah1.y, Bh1.x, Bh1.y);
    MMA_BF16(a1, Ah0.x, Ah1.x, Ah0.y, Ah1.y, Bl1.x, Bl1.y);
    MMA_BF16(a1, Al0.x, Al1.x, Al0.y, Al1.y, Bh1.x, Bh1.y);
  }
}

__device__ __forceinline__ void epilogue(
    const float* a0, const float* a1, float* creg, float4 bu,
    int row0, int by, int tid, int wm, int wn, int g, int q,
    uint32_t* __restrict__ outHi, uint32_t* __restrict__ outLo,
    float* __restrict__ outF, float* gsm) {
  __syncthreads();
  int col0 = wn + 2 * q, col1 = wn + 8 + 2 * q;
  gsm[(wm + g) * 65 + col0] = a0[0];     gsm[(wm + g) * 65 + col0 + 1] = a0[1];
  gsm[(wm + g + 8) * 65 + col0] = a0[2]; gsm[(wm + g + 8) * 65 + col0 + 1] = a0[3];
  gsm[(wm + g) * 65 + col1] = a1[0];     gsm[(wm + g) * 65 + col1 + 1] = a1[1];
  gsm[(wm + g + 8) * 65 + col1] = a1[2]; gsm[(wm + g + 8) * 65 + col1 + 1] = a1[3];
  __syncthreads();
  float* hbuf = gsm + 2112;
#pragma unroll
  for (int uu = 0; uu < 2; ++uu) {
    int e = tid + uu * 256, r = e >> 4, hid = e & 15;
    float gi = gsm[r * 65 + hid] + bu.x;
    float gf = gsm[r * 65 + 16 + hid] + bu.y;
    float gg = gsm[r * 65 + 32 + hid] + bu.z;
    float go = gsm[r * 65 + 48 + hid] + bu.w;
    float si = 1.f / (1.f + expf(-gi));
    float sf = 1.f / (1.f + expf(-gf));
    float so = 1.f / (1.f + expf(-go));
    float cn = sf * creg[uu] + si * tanhf(gg);
    float hn = so * tanhf(cn);
    creg[uu] = cn;
    hbuf[r * 17 + hid] = hn;
    if (outF) outF[(size_t)(row0 + r) * HSZ + by * 16 + hid] = hn;
  }
  __syncthreads();
  int pr = tid >> 3, jj = tid & 7, lp = j2lp(jj);
  uint32_t hi, lo;
  split2(hbuf[pr * 17 + 2 * lp], hbuf[pr * 17 + 2 * lp + 1], hi, lo);
  size_t o = (size_t)(row0 + pr) * PH + by * 8 + jj;
  outHi[o] = hi;
  outLo[o] = lo;
}

__device__ __forceinline__ float4 bias4(const float* b, int gh) {
  return make_float4(b[gh], b[HSZ + gh], b[2 * HSZ + gh], b[3 * HSZ + gh]);
}

#define SYNC_ST(GC, SW)                                                       \
  __syncthreads();                                                            \
  st_grp<GC, SW>(rA, rW, sA, sWst, tid);                                      \
  __syncthreads()

// ---------------- persistent kernel: all 432 steps ----------------
__global__ __launch_bounds__(256) void lstm_persist(
    const float* __restrict__ eb0, const float* __restrict__ eb1,
    const float* __restrict__ db0, const float* __restrict__ db1) {
  extern __shared__ uint32_t smem[];
  int tid = threadIdx.x;
  int bx = blockIdx.x & 7, by = blockIdx.x >> 3;
  int row0 = bx * 32;
  int lane = tid & 31, wid = tid >> 5, g = lane >> 2, q = lane & 3;
  int wm = (wid & 1) * 16, wn = (wid >> 1) * 16;
  int aoff = (wm + g) * 8 + 2 * q;
  int boff0 = (wn + g) * 8 + 2 * q, boff1 = (wn + 8 + g) * 8 + 2 * q;
  uint32_t* sA = smem + 49152;
  uint32_t* sWst = smem + 53248;
  float* gsm = (float*)sA;
  int gh = by * 16 + (tid & 15);
  float c0r[2] = {0.f, 0.f}, c1r[2] = {0.f, 0.f};
  unsigned bt = 0;
  int par = 0;
  uint2 rA[8], rW[8];

  // ---- encoder phase ----
  ld_res(smem + 0,     g_eWhh0h, 128, by, tid);
  ld_res(smem + 8192,  g_eWhh0l, 128, by, tid);
  ld_res(smem + 16384, g_eWih1h, 128, by, tid);
  ld_res(smem + 24576, g_eWih1l, 128, by, tid);
  ld_res(smem + 32768, g_eWhh1h, 128, by, tid);
  ld_res(smem + 40960, g_eWhh1l, 128, by, tid);
  ld_res(sWst,         g_eWih0h, 16, by, tid);
  ld_res(sWst + 1024,  g_eWih0l, 16, by, tid);
  float4 be0 = bias4(eb0, gh), be1 = bias4(eb1, gh);

  for (int t = 0; t < TIN; ++t) {
    const uint32_t *h0h = g_h0hi[par], *h0l = g_h0lo[par];
    const uint32_t *h1h = g_h1hi[par], *h1l = g_h1lo[par];
    {  // L0: x(2) + h0(8,8)
      float a0[4] = {}, a1[4] = {};
      ld_grp<2, false>(rA, rW, g_xhi + (size_t)t * PX, g_xlo + (size_t)t * PX,
                       TIN * PX, 0, row0, tid);
      SYNC_ST(2, false);
      ld_grp<8, false>(rA, rW, h0h, h0l, PH, 0, row0, tid);
      comp_grp<2>(a0, a1, sA, sWst, sWst + 1024, aoff, boff0, boff1);
      SYNC_ST(8, false);
      ld_grp<8, false>(rA, rW, h0h + 64, h0l + 64, PH, 0, row0, tid);
      comp_grp<8>(a0, a1, sA, smem + 0, smem + 8192, aoff, boff0, boff1);
      SYNC_ST(8, false);
      comp_grp<8>(a0, a1, sA, smem + 4096, smem + 12288, aoff, boff0, boff1);
      epilogue(a0, a1, c0r, be0, row0, by, tid, wm, wn, g, q,
               g_h0hi[par ^ 1], g_h0lo[par ^ 1], nullptr, gsm);
    }
    bt += NCTA; gbar(bt);
    {  // L1: h0new(8,8 Wih1) + h1old(8,8 Whh1)
      const uint32_t *nh = g_h0hi[par ^ 1], *nl = g_h0lo[par ^ 1];
      float a0[4] = {}, a1[4] = {};
      ld_grp<8, false>(rA, rW, nh, nl, PH, 0, row0, tid);
      SYNC_ST(8, false);
      ld_grp<8, false>(rA, rW, nh + 64, nl + 64, PH, 0, row0, tid);
      comp_grp<8>(a0, a1, sA, smem + 16384, smem + 24576, aoff, boff0, boff1);
      SYNC_ST(8, false);
      ld_grp<8, false>(rA, rW, h1h, h1l, PH, 0, row0, tid);
      comp_grp<8>(a0, a1, sA, smem + 20480, smem + 28672, aoff, boff0, boff1);
      SYNC_ST(8, false);
      ld_grp<8, false>(rA, rW, h1h + 64, h1l + 64, PH, 0, row0, tid);
      comp_grp<8>(a0, a1, sA, smem + 32768, smem + 40960, aoff, boff0, boff1);
      SYNC_ST(8, false);
      comp_grp<8>(a0, a1, sA, smem + 36864, smem + 45056, aoff, boff0, boff1);
      epilogue(a0, a1, c1r, be1, row0, by, tid, wm, wn, g, q,
               g_h1hi[par ^ 1], g_h1lo[par ^ 1], nullptr, gsm);
    }
    bt += NCTA; gbar(bt);
    par ^= 1;
  }

  // ---- decoder phase ----
  ld_res(smem + 0,     g_Wph,    128, by, tid);
  ld_res(smem + 8192,  g_Wpl,    128, by, tid);
  ld_res(smem + 16384, g_dWhh0h, 128, by, tid);
  ld_res(smem + 24576, g_dWhh0l, 128, by, tid);
  ld_res(smem + 32768, g_dWih1h, 128, by, tid);
  ld_res(smem + 40960, g_dWhh1h, 128, by, tid);
  ld_res(sWst,         g_dWih0h, 16, by, tid);
  ld_res(sWst + 1024,  g_dWih0l, 16, by, tid);
  __syncthreads();
  const uint32_t* ih1lo = g_dWih1l + (size_t)by * 64 * PH;
  const uint32_t* hh1lo = g_dWhh1l + (size_t)by * 64 * PH;
  float4 bd0 = bias4(db0, gh), bdp = bias4(g_bp, gh), bd1 = bias4(db1, gh);

  for (int s = 0; s < TOUT; ++s) {
    const uint32_t *h0h = g_h0hi[par], *h0l = g_h0lo[par];
    const uint32_t *h1h = g_h1hi[par], *h1l = g_h1lo[par];
    {  // L0
      float a0[4] = {}, a1[4] = {};
      if (s == 0) {  // x(2, dWih0) + h0(8,8 Whh0)
        ld_grp<2, false>(rA, rW, g_xhi + (size_t)(TIN - 1) * PX,
                         g_xlo + (size_t)(TIN - 1) * PX, TIN * PX, 0, row0, tid);
        SYNC_ST(2, false);
        ld_grp<8, false>(rA, rW, h0h, h0l, PH, 0, row0, tid);
        comp_grp<2>(a0, a1, sA, sWst, sWst + 1024, aoff, boff0, boff1);
        SYNC_ST(8, false);
        ld_grp<8, false>(rA, rW, h0h + 64, h0l + 64, PH, 0, row0, tid);
        comp_grp<8>(a0, a1, sA, smem + 16384, smem + 24576, aoff, boff0, boff1);
        SYNC_ST(8, false);
        comp_grp<8>(a0, a1, sA, smem + 20480, smem + 28672, aoff, boff0, boff1);
        epilogue(a0, a1, c0r, bd0, row0, by, tid, wm, wn, g, q,
                 g_h0hi[par ^ 1], g_h0lo[par ^ 1], nullptr, gsm);
      } else {  // h1old(8,8 Wp) + h0old(8,8 Whh0)
        ld_grp<8, false>(rA, rW, h1h, h1l, PH, 0, row0, tid);
        SYNC_ST(8, false);
        ld_grp<8, false>(rA, rW, h1h + 64, h1l + 64, PH, 0, row0, tid);
        comp_grp<8>(a0, a1, sA, smem + 0, smem + 8192, aoff, boff0, boff1);
        SYNC_ST(8, false);
        ld_grp<8, false>(rA, rW, h0h, h0l, PH, 0, row0, tid);
        comp_grp<8>(a0, a1, sA, smem + 4096, smem + 12288, aoff, boff0, boff1);
        SYNC_ST(8, false);
        ld_grp<8, false>(rA, rW, h0h + 64, h0l + 64, PH, 0, row0, tid);
        comp_grp<8>(a0, a1, sA, smem + 16384, smem + 24576, aoff, boff0, boff1);
        SYNC_ST(8, false);
        comp_grp<8>(a0, a1, sA, smem + 20480, smem + 28672, aoff, boff0, boff1);
        epilogue(a0, a1, c0r, bdp, row0, by, tid, wm, wn, g, q,
                 g_h0hi[par ^ 1], g_h0lo[par ^ 1], nullptr, gsm);
      }
    }
    bt += NCTA; gbar(bt);
    {  // L1: h0new(8,8 Wih1 lo-streamed) + h1old(8,8 Whh1 lo-streamed)
      const uint32_t *nh = g_h0hi[par ^ 1], *nl = g_h0lo[par ^ 1];
      float a0[4] = {}, a1[4] = {};
      ld_grp<8, true>(rA, rW, nh, nl, PH, ih1lo, row0, tid);
      SYNC_ST(8, true);
      ld_grp<8, true>(rA, rW, nh + 64, nl + 64, PH, ih1lo + 64, row0, tid);
      comp_grp<8>(a0, a1, sA, smem + 32768, sWst, aoff, boff0, boff1);
      SYNC_ST(8, true);
      ld_grp<8, true>(rA, rW, h1h, h1l, PH, hh1lo, row0, tid);
      comp_grp<8>(a0, a1, sA, smem + 36864, sWst, aoff, boff0, boff1);
      SYNC_ST(8, true);
      ld_grp<8, true>(rA, rW, h1h + 64, h1l + 64, PH, hh1lo + 64, row0, tid);
      comp_grp<8>(a0, a1, sA, smem + 40960, sWst, aoff, boff0, boff1);
      SYNC_ST(8, true);
      comp_grp<8>(a0, a1, sA, smem + 45056, sWst, aoff, boff0, boff1);
      epilogue(a0, a1, c1r, bd1, row0, by, tid, wm, wn, g, q,
               g_h1hi[par ^ 1], g_h1lo[par ^ 1],
               g_h1s + (size_t)s * BSZ * HSZ, gsm);
    }
    bt += NCTA; gbar(bt);
    par ^= 1;
  }
}

// ---------------- final projection ----------------
__global__ __launch_bounds__(256) void out_proj(const float* __restrict__ Wout,
                                                const float* __restrict__ bout,
                                                float* __restrict__ out) {
  __shared__ float hs[32][65];
  __shared__ float wsT[64][36];
  int tid = threadIdx.x;
  int b0 = blockIdx.x * 32, s = blockIdx.y;
  int bloc = tid & 31, f0 = (tid >> 5) * 4;
  float acc[4] = {0.f, 0.f, 0.f, 0.f};
  const float* hsrc = g_h1s + (size_t)s * BSZ * HSZ;
  for (int k0 = 0; k0 < HSZ; k0 += 64) {
    __syncthreads();
#pragma unroll
    for (int qq = 0; qq < 2; ++qq) {
      int idx = tid + qq * 256, row = idx >> 4, kq = idx & 15;
      float4 v = *(const float4*)(hsrc + (size_t)(b0 + row) * HSZ + k0 + kq * 4);
      hs[row][kq * 4 + 0] = v.x; hs[row][kq * 4 + 1] = v.y;
      hs[row][kq * 4 + 2] = v.z; hs[row][kq * 4 + 3] = v.w;
      float4 w = *(const float4*)(Wout + (size_t)row * HSZ + k0 + kq * 4);
      wsT[kq * 4 + 0][row] = w.x; wsT[kq * 4 + 1][row] = w.y;
      wsT[kq * 4 + 2][row] = w.z; wsT[kq * 4 + 3][row] = w.w;
    }
    __syncthreads();
#pragma unroll 8
    for (int kk = 0; kk < 64; ++kk) {
      float hv = hs[bloc][kk];
      float4 w = *(const float4*)&wsT[kk][f0];
      acc[0] += hv * w.x; acc[1] += hv * w.y;
      acc[2] += hv * w.z; acc[3] += hv * w.w;
    }
  }
  float* op = out + (size_t)(b0 + bloc) * TOUT * FSZ + s * FSZ + f0;
  op[0] = acc[0] + bout[f0 + 0];
  op[1] = acc[1] + bout[f0 + 1];
  op[2] = acc[2] + bout[f0 + 2];
  op[3] = acc[3] + bout[f0 + 3];
}

// ---------------- host ----------------
extern "C" void kernel_launch(void* const* d_in, const int* in_sizes, int n_in,
                              void* d_out, int out_size) {
  (void)in_sizes; (void)n_in; (void)out_size;
  const float* x     = (const float*)d_in[0];
  const float* eWih0 = (const float*)d_in[1];
  const float* eWhh0 = (const float*)d_in[2];
  const float* eb0   = (const float*)d_in[3];
  const float* eWih1 = (const float*)d_in[4];
  const float* eWhh1 = (const float*)d_in[5];
  const float* eb1   = (const float*)d_in[6];
  const float* dWih0 = (const float*)d_in[7];
  const float* dWhh0 = (const float*)d_in[8];
  const float* db0   = (const float*)d_in[9];
  const float* dWih1 = (const float*)d_in[10];
  const float* dWhh1 = (const float*)d_in[11];
  const float* db1   = (const float*)d_in[12];
  const float* dWout = (const float*)d_in[13];
  const float* dbout = (const float*)d_in[14];

  void* p;
  cudaGetSymbolAddress(&p, g_Wp);      float* Wp = (float*)p;
  cudaGetSymbolAddress(&p, g_eWih0h);  uint32_t* eWih0h = (uint32_t*)p;
  cudaGetSymbolAddress(&p, g_eWih0l);  uint32_t* eWih0l = (uint32_t*)p;
  cudaGetSymbolAddress(&p, g_eWhh0h);  uint32_t* eWhh0h = (uint32_t*)p;
  cudaGetSymbolAddress(&p, g_eWhh0l);  uint32_t* eWhh0l = (uint32_t*)p;
  cudaGetSymbolAddress(&p, g_eWih1h);  uint32_t* eWih1h = (uint32_t*)p;
  cudaGetSymbolAddress(&p, g_eWih1l);  uint32_t* eWih1l = (uint32_t*)p;
  cudaGetSymbolAddress(&p, g_eWhh1h);  uint32_t* eWhh1h = (uint32_t*)p;
  cudaGetSymbolAddress(&p, g_eWhh1l);  uint32_t* eWhh1l = (uint32_t*)p;
  cudaGetSymbolAddress(&p, g_dWih0h);  uint32_t* dWih0h = (uint32_t*)p;
  cudaGetSymbolAddress(&p, g_dWih0l);  uint32_t* dWih0l = (uint32_t*)p;
  cudaGetSymbolAddress(&p, g_dWhh0h);  uint32_t* dWhh0h = (uint32_t*)p;
  cudaGetSymbolAddress(&p, g_dWhh0l);  uint32_t* dWhh0l = (uint32_t*)p;
  cudaGetSymbolAddress(&p, g_dWih1h);  uint32_t* dWih1h = (uint32_t*)p;
  cudaGetSymbolAddress(&p, g_dWih1l);  uint32_t* dWih1l = (uint32_t*)p;
  cudaGetSymbolAddress(&p, g_dWhh1h);  uint32_t* dWhh1h = (uint32_t*)p;
  cudaGetSymbolAddress(&p, g_dWhh1l);  uint32_t* dWhh1l = (uint32_t*)p;
  cudaGetSymbolAddress(&p, g_Wph);     uint32_t* Wph = (uint32_t*)p;
  cudaGetSymbolAddress(&p, g_Wpl);     uint32_t* Wpl = (uint32_t*)p;

  cudaFuncSetAttribute(lstm_persist, cudaFuncAttributeMaxDynamicSharedMemorySize,
                       SMW * 4);

  zero_init_kernel<<<(BSZ * PH) / 256, 256>>>();
  wp_kernel<<<4 * HSZ, 256>>>(dWih0, dWout);
  bp_kernel<<<(4 * HSZ) / 256, 256>>>(dWih0, db0, dbout);
  pack_x<<<(BSZ * TIN * PX) / 256, 256>>>(x);
  pack_w<<<(1024 * 16) / 256, 256>>>(eWih0, 32, eWih0h, eWih0l);
  pack_w<<<(1024 * 128) / 256, 256>>>(eWhh0, 256, eWhh0h, eWhh0l);
  pack_w<<<(1024 * 128) / 256, 256>>>(eWih1, 256, eWih1h, eWih1l);
  pack_w<<<(1024 * 128) / 256, 256>>>(eWhh1, 256, eWhh1h, eWhh1l);
  pack_w<<<(1024 * 16) / 256, 256>>>(dWih0, 32, dWih0h, dWih0l);
  pack_w<<<(1024 * 128) / 256, 256>>>(dWhh0, 256, dWhh0h, dWhh0l);
  pack_w<<<(1024 * 128) / 256, 256>>>(dWih1, 256, dWih1h, dWih1l);
  pack_w<<<(1024 * 128) / 256, 256>>>(dWhh1, 256, dWhh1h, dWhh1l);
  pack_w<<<(1024 * 128) / 256, 256>>>(Wp, 256, Wph, Wpl);

  lstm_persist<<<NCTA, 256, SMW * 4>>>(eb0, eb1, db0, db1);
  out_proj<<<dim3(BSZ / 32, TOUT), 256>>>(dWout, dbout, (float*)d_out);
}

// round 13
// speedup vs baseline: 2.1041x; 1.0996x over previous
#include <cuda_runtime.h>
#include <cuda_bf16.h>
#include <math.h>
#include <stdint.h>

#define BSZ 256
#define HSZ 256
#define TIN 336
#define TOUT 96
#define FSZ 32
#define PH 128
#define PX 16
#define NCTA 128
#define SMW 57344

__device__ uint32_t g_h0hi[2][BSZ * PH], g_h0lo[2][BSZ * PH];
__device__ uint32_t g_h1hi[2][BSZ * PH], g_h1lo[2][BSZ * PH];
__device__ uint32_t g_xhi[BSZ * TIN * PX], g_xlo[BSZ * TIN * PX];
__device__ float g_Wp[4 * HSZ * HSZ], g_bp[4 * HSZ];
__device__ float g_h1s[(size_t)TOUT * BSZ * HSZ];
__device__ unsigned g_gbar[8 * 32];

__device__ uint32_t g_eWih0h[1024 * 16],  g_eWih0l[1024 * 16];
__device__ uint32_t g_eWhh0h[1024 * 128], g_eWhh0l[1024 * 128];
__device__ uint32_t g_eWih1h[1024 * 128], g_eWih1l[1024 * 128];
__device__ uint32_t g_eWhh1h[1024 * 128], g_eWhh1l[1024 * 128];
__device__ uint32_t g_dWih0h[1024 * 16],  g_dWih0l[1024 * 16];
__device__ uint32_t g_dWhh0h[1024 * 128], g_dWhh0l[1024 * 128];
__device__ uint32_t g_dWih1h[1024 * 128], g_dWih1l[1024 * 128];
__device__ uint32_t g_dWhh1h[1024 * 128], g_dWhh1l[1024 * 128];
__device__ uint32_t g_Wph[1024 * 128],    g_Wpl[1024 * 128];

__device__ __forceinline__ int j2lp(int j) { return ((j & 1) << 2) | (j >> 1); }

__device__ __forceinline__ void split2(float v0, float v1, uint32_t& hi, uint32_t& lo) {
  __nv_bfloat16 h0 = __float2bfloat16_rn(v0), h1 = __float2bfloat16_rn(v1);
  __nv_bfloat16 l0 = __float2bfloat16_rn(v0 - __bfloat162float(h0));
  __nv_bfloat16 l1 = __float2bfloat16_rn(v1 - __bfloat162float(h1));
  __nv_bfloat162 ph = __nv_bfloat162(h0, h1), pl = __nv_bfloat162(l0, l1);
  hi = *(uint32_t*)&ph;
  lo = *(uint32_t*)&pl;
}

#define MMA_BF16(C, a0, a1, a2, a3, b0, b1)                                   \
  asm volatile(                                                               \
      "mma.sync.aligned.m16n8k16.row.col.f32.bf16.bf16.f32 "                  \
      "{%0,%1,%2,%3},{%4,%5,%6,%7},{%8,%9},{%0,%1,%2,%3};"                    \
      : "+f"(C[0]), "+f"(C[1]), "+f"(C[2]), "+f"(C[3])                        \
      : "r"(a0), "r"(a1), "r"(a2), "r"(a3), "r"(b0), "r"(b1))

#define LDG_CG2(v, p)                                                         \
  asm volatile("ld.global.cg.v2.u32 {%0,%1},[%2];"                            \
               : "=r"((v).x), "=r"((v).y) : "l"(p))

// ---------------- init / preprocess ----------------
__global__ void zero_init_kernel() {
  int i = blockIdx.x * blockDim.x + threadIdx.x;
  g_h0hi[0][i] = 0u; g_h0lo[0][i] = 0u;
  g_h1hi[0][i] = 0u; g_h1lo[0][i] = 0u;
  if (i < 256) g_gbar[i] = 0u;
}

__global__ void wp_kernel(const float* __restrict__ Wih0, const float* __restrict__ Wout) {
  __shared__ float wr[FSZ];
  int c = blockIdx.x;
  if (threadIdx.x < FSZ) wr[threadIdx.x] = Wih0[c * FSZ + threadIdx.x];
  __syncthreads();
  int k = threadIdx.x;
  float acc = 0.f;
#pragma unroll
  for (int f = 0; f < FSZ; ++f) acc += wr[f] * Wout[f * HSZ + k];
  g_Wp[c * HSZ + k] = acc;
}

__global__ void bp_kernel(const float* __restrict__ Wih0, const float* __restrict__ b0,
                          const float* __restrict__ bout) {
  int c = blockIdx.x * blockDim.x + threadIdx.x;
  float acc = b0[c];
#pragma unroll
  for (int f = 0; f < FSZ; ++f) acc += Wih0[c * FSZ + f] * bout[f];
  g_bp[c] = acc;
}

// gate-interleaved packing: packed col n -> gate/hid so each mma thread's
// accumulators hold {i,f,g,o} of ONE hidden unit.
__global__ void pack_w(const float* __restrict__ W, int K,
                       uint32_t* __restrict__ ohi, uint32_t* __restrict__ olo) {
  int P = K >> 1;
  int idx = blockIdx.x * 256 + threadIdx.x;
  if (idx >= 1024 * P) return;
  int pr = idx / P, w = idx % P;
  int n = pr & 63, by = pr >> 6;
  int eps = (n >> 3) & 1, qq = (n >> 1) & 3, dlt = n & 1;
  int gate = 2 * eps + dlt;
  int hid = ((n >> 4) << 2) + qq;
  int r = gate * 256 + by * 16 + hid;
  int cch = w >> 3, j = w & 7;
  int k0 = cch * 16 + 2 * j2lp(j);
  split2(W[r * K + k0], W[r * K + k0 + 1], ohi[idx], olo[idx]);
}

__global__ void pack_x(const float* __restrict__ x) {
  int idx = blockIdx.x * 256 + threadIdx.x;
  int w = idx & (PX - 1), bt = idx >> 4;
  int cch = w >> 3, j = w & 7;
  int k0 = cch * 16 + 2 * j2lp(j);
  const float* src = x + (size_t)bt * FSZ + k0;
  split2(src[0], src[1], g_xhi[idx], g_xlo[idx]);
}

// ---------------- persistent building blocks ----------------
__device__ __forceinline__ void gbar(int grp, unsigned target) {
  __syncthreads();
  __threadfence();
  if (threadIdx.x == 0) {
    atomicAdd(&g_gbar[grp * 32], 1u);
    volatile unsigned* p = &g_gbar[grp * 32];
    while (*p < target) {}
  }
  __syncthreads();
}

__device__ __forceinline__ void ld_res(uint32_t* dst, const uint32_t* src,
                                       int P, int by, int tid) {
  const uint32_t* s = src + (size_t)(by * 64) * P;
  for (int idx = tid * 2; idx < 64 * P; idx += 512) {
    int rw = idx / P, w = idx - rw * P;
    int c = w >> 3, j = w & 7;
    uint2 v = *(const uint2*)(s + (size_t)rw * P + w);
    *(uint2*)&dst[c * 512 + rw * 8 + j] = v;
  }
}

template <int GC, bool SW>
__device__ __forceinline__ void ld_grp(uint2* rA, uint2* rW,
    const uint32_t* __restrict__ ahi, const uint32_t* __restrict__ alo,
    int lda, const uint32_t* __restrict__ gwl, int row0, int tid) {
#pragma unroll
  for (int it = 0; it < GC / 2; ++it) {
    int idx = tid * 2 + it * 512;
    int rw = (idx & 255) >> 3, j = idx & 7, c = idx >> 8;
    size_t go = (size_t)(row0 + rw) * lda + (c << 3) + j;
    LDG_CG2(rA[2 * it], ahi + go);
    LDG_CG2(rA[2 * it + 1], alo + go);
  }
  if (SW) {
#pragma unroll
    for (int it = 0; it < GC; ++it) {
      int idx = tid * 2 + it * 512;
      int rw = (idx & 511) >> 3, j = idx & 7, c = idx >> 9;
      LDG_CG2(rW[it], gwl + rw * PH + (c << 3) + j);
    }
  }
}

template <int GC, bool SW>
__device__ __forceinline__ void st_grp(const uint2* rA, const uint2* rW,
                                       uint32_t* sA, uint32_t* sWst, int tid) {
#pragma unroll
  for (int it = 0; it < GC / 2; ++it) {
    int idx = tid * 2 + it * 512;
    *(uint2*)&sA[idx] = rA[2 * it];
    *(uint2*)&sA[2048 + idx] = rA[2 * it + 1];
  }
  if (SW) {
#pragma unroll
    for (int it = 0; it < GC; ++it)
      *(uint2*)&sWst[tid * 2 + it * 512] = rW[it];
  }
}

template <int GC>
__device__ __forceinline__ void comp_grp(float* a0, float* a1,
    const uint32_t* sA, const uint32_t* swh, const uint32_t* swl,
    int aoff, int boff0, int boff1) {
#pragma unroll
  for (int c = 0; c < GC; ++c) {
    const uint32_t* bAh = sA + (c << 8);
    const uint32_t* bAl = bAh + 2048;
    const uint32_t* bWh = swh + (c << 9);
    const uint32_t* bWl = swl + (c << 9);
    uint2 Ah0 = *(const uint2*)(bAh + aoff), Ah1 = *(const uint2*)(bAh + aoff + 64);
    uint2 Al0 = *(const uint2*)(bAl + aoff), Al1 = *(const uint2*)(bAl + aoff + 64);
    uint2 Bh0 = *(const uint2*)(bWh + boff0), Bl0 = *(const uint2*)(bWl + boff0);
    uint2 Bh1 = *(const uint2*)(bWh + boff1), Bl1 = *(const uint2*)(bWl + boff1);
    MMA_BF16(a0, Ah0.x, Ah1.x, Ah0.y, Ah1.y, Bh0.x, Bh0.y);
    MMA_BF16(a0, Ah0.x, Ah1.x, Ah0.y, Ah1.y, Bl0.x, Bl0.y);
    MMA_BF16(a0, Al0.x, Al1.x, Al0.y, Al1.y, Bh0.x, Bh0.y);
    MMA_BF16(a1, Ah0.x, Ah1.x, Ah0.y, Ah1.y, Bh1.x, Bh1.y);
    MMA_BF16(a1, Ah0.x, Ah1.x, Ah0.y, Ah1.y, Bl1.x, Bl1.y);
    MMA_BF16(a1, Al0.x, Al1.x, Al0.y, Al1.y, Bh1.x, Bh1.y);
  }
}

// register-resident pointwise: a0 = {i,f}x2rows, a1 = {g,o}x2rows of hid hidT
__device__ __forceinline__ void epilogue(
    const float* a0, const float* a1, float* creg, float4 bu,
    int row0, int by, int tid, int wm, int g_, int hidT,
    uint32_t* __restrict__ outHi, uint32_t* __restrict__ outLo,
    float* __restrict__ outF, float* hbuf) {
  __syncthreads();
#pragma unroll
  for (int uu = 0; uu < 2; ++uu) {
    int row = wm + g_ + 8 * uu;
    float gi = (uu ? a0[2] : a0[0]) + bu.x;
    float gf = (uu ? a0[3] : a0[1]) + bu.y;
    float gg = (uu ? a1[2] : a1[0]) + bu.z;
    float go = (uu ? a1[3] : a1[1]) + bu.w;
    float si = 1.f / (1.f + expf(-gi));
    float sf = 1.f / (1.f + expf(-gf));
    float so = 1.f / (1.f + expf(-go));
    float cn = sf * creg[uu] + si * tanhf(gg);
    float hn = so * tanhf(cn);
    creg[uu] = cn;
    hbuf[row * 17 + hidT] = hn;
    if (outF) outF[(size_t)(row0 + row) * HSZ + by * 16 + hidT] = hn;
  }
  __syncthreads();
  int pr = tid >> 3, jj = tid & 7, lp = j2lp(jj);
  uint32_t hi, lo;
  split2(hbuf[pr * 17 + 2 * lp], hbuf[pr * 17 + 2 * lp + 1], hi, lo);
  size_t o = (size_t)(row0 + pr) * PH + by * 8 + jj;
  outHi[o] = hi;
  outLo[o] = lo;
}

__device__ __forceinline__ float4 bias4(const float* b, int gh) {
  return make_float4(b[gh], b[HSZ + gh], b[2 * HSZ + gh], b[3 * HSZ + gh]);
}

#define SYNC_ST(GC, SW)                                                       \
  __syncthreads();                                                            \
  st_grp<GC, SW>(rA, rW, sA, sWst, tid);                                      \
  __syncthreads()

// ---------------- persistent kernel ----------------
__global__ __launch_bounds__(256) void lstm_persist(
    const float* __restrict__ eb0, const float* __restrict__ eb1,
    const float* __restrict__ db0, const float* __restrict__ db1) {
  extern __shared__ uint32_t smem[];
  int tid = threadIdx.x;
  int bx = blockIdx.x & 7, by = blockIdx.x >> 3;
  int row0 = bx * 32;
  int lane = tid & 31, wid = tid >> 5, g_ = lane >> 2, q = lane & 3;
  int wm = (wid & 1) * 16, wn = (wid >> 1) * 16;
  int hidT = (wn >> 2) + q;
  int aoff = (wm + g_) * 8 + 2 * q;
  int boff0 = (wn + g_) * 8 + 2 * q, boff1 = (wn + 8 + g_) * 8 + 2 * q;
  uint32_t* sA = smem + 49152;
  uint32_t* sWst = smem + 53248;
  float* hbuf = (float*)sA;
  int gh = by * 16 + hidT;
  float c0r[2] = {0.f, 0.f}, c1r[2] = {0.f, 0.f};
  unsigned bt = 0;
  int par = 0;
  uint2 rA[8], rW[8];

  // ---- encoder ----
  ld_res(smem + 0,     g_eWhh0h, 128, by, tid);
  ld_res(smem + 8192,  g_eWhh0l, 128, by, tid);
  ld_res(smem + 16384, g_eWih1h, 128, by, tid);
  ld_res(smem + 24576, g_eWih1l, 128, by, tid);
  ld_res(smem + 32768, g_eWhh1h, 128, by, tid);
  ld_res(smem + 40960, g_eWhh1l, 128, by, tid);
  ld_res(sWst,         g_eWih0h, 16, by, tid);
  ld_res(sWst + 1024,  g_eWih0l, 16, by, tid);
  float4 be0 = bias4(eb0, gh), be1 = bias4(eb1, gh);

  for (int t = 0; t < TIN; ++t) {
    const uint32_t *h0h = g_h0hi[par], *h0l = g_h0lo[par];
    const uint32_t *h1h = g_h1hi[par], *h1l = g_h1lo[par];
    {  // L0: x @ Wih0 + h0old @ Whh0  (all operands visible)
      float a0[4] = {}, a1[4] = {};
      ld_grp<2, false>(rA, rW, g_xhi + (size_t)t * PX, g_xlo + (size_t)t * PX,
                       TIN * PX, 0, row0, tid);
      SYNC_ST(2, false);
      ld_grp<8, false>(rA, rW, h0h, h0l, PH, 0, row0, tid);
      comp_grp<2>(a0, a1, sA, sWst, sWst + 1024, aoff, boff0, boff1);
      SYNC_ST(8, false);
      ld_grp<8, false>(rA, rW, h0h + 64, h0l + 64, PH, 0, row0, tid);
      comp_grp<8>(a0, a1, sA, smem + 0, smem + 8192, aoff, boff0, boff1);
      SYNC_ST(8, false);
      comp_grp<8>(a0, a1, sA, smem + 4096, smem + 12288, aoff, boff0, boff1);
      epilogue(a0, a1, c0r, be0, row0, by, tid, wm, g_, hidT,
               g_h0hi[par ^ 1], g_h0lo[par ^ 1], nullptr, hbuf);
    }
    bt += 16; gbar(bx, bt);   // single barrier per timestep
    {  // L1: h1old @ Whh1 first, then h0new @ Wih1
      const uint32_t *nh = g_h0hi[par ^ 1], *nl = g_h0lo[par ^ 1];
      float a0[4] = {}, a1[4] = {};
      ld_grp<8, false>(rA, rW, h1h, h1l, PH, 0, row0, tid);
      SYNC_ST(8, false);
      ld_grp<8, false>(rA, rW, h1h + 64, h1l + 64, PH, 0, row0, tid);
      comp_grp<8>(a0, a1, sA, smem + 32768, smem + 40960, aoff, boff0, boff1);
      SYNC_ST(8, false);
      ld_grp<8, false>(rA, rW, nh, nl, PH, 0, row0, tid);
      comp_grp<8>(a0, a1, sA, smem + 36864, smem + 45056, aoff, boff0, boff1);
      SYNC_ST(8, false);
      ld_grp<8, false>(rA, rW, nh + 64, nl + 64, PH, 0, row0, tid);
      comp_grp<8>(a0, a1, sA, smem + 16384, smem + 24576, aoff, boff0, boff1);
      SYNC_ST(8, false);
      comp_grp<8>(a0, a1, sA, smem + 20480, smem + 28672, aoff, boff0, boff1);
      epilogue(a0, a1, c1r, be1, row0, by, tid, wm, g_, hidT,
               g_h1hi[par ^ 1], g_h1lo[par ^ 1], nullptr, hbuf);
    }
    par ^= 1;
  }

  // ---- decoder ----
  ld_res(smem + 0,     g_Wph,    128, by, tid);
  ld_res(smem + 8192,  g_Wpl,    128, by, tid);
  ld_res(smem + 16384, g_dWhh0h, 128, by, tid);
  ld_res(smem + 24576, g_dWhh0l, 128, by, tid);
  ld_res(smem + 32768, g_dWih1h, 128, by, tid);
  ld_res(smem + 40960, g_dWhh1h, 128, by, tid);
  ld_res(sWst,         g_dWih0h, 16, by, tid);
  ld_res(sWst + 1024,  g_dWih0l, 16, by, tid);
  __syncthreads();
  const uint32_t* ih1lo = g_dWih1l + (size_t)by * 64 * PH;
  const uint32_t* hh1lo = g_dWhh1l + (size_t)by * 64 * PH;
  float4 bd0 = bias4(db0, gh), bdp = bias4(g_bp, gh), bd1 = bias4(db1, gh);

  for (int s = 0; s < TOUT; ++s) {
    const uint32_t *h0h = g_h0hi[par], *h0l = g_h0lo[par];
    const uint32_t *h1h = g_h1hi[par], *h1l = g_h1lo[par];
    {  // L0
      float a0[4] = {}, a1[4] = {};
      if (s == 0) {
        ld_grp<2, false>(rA, rW, g_xhi + (size_t)(TIN - 1) * PX,
                         g_xlo + (size_t)(TIN - 1) * PX, TIN * PX, 0, row0, tid);
        SYNC_ST(2, false);
        ld_grp<8, false>(rA, rW, h0h, h0l, PH, 0, row0, tid);
        comp_grp<2>(a0, a1, sA, sWst, sWst + 1024, aoff, boff0, boff1);
        SYNC_ST(8, false);
        ld_grp<8, false>(rA, rW, h0h + 64, h0l + 64, PH, 0, row0, tid);
        comp_grp<8>(a0, a1, sA, smem + 16384, smem + 24576, aoff, boff0, boff1);
        SYNC_ST(8, false);
        comp_grp<8>(a0, a1, sA, smem + 20480, smem + 28672, aoff, boff0, boff1);
        epilogue(a0, a1, c0r, bd0, row0, by, tid, wm, g_, hidT,
                 g_h0hi[par ^ 1], g_h0lo[par ^ 1], nullptr, hbuf);
      } else {  // h0old @ Whh0 first (older), then h1 @ Wp (fresh)
        ld_grp<8, false>(rA, rW, h0h, h0l, PH, 0, row0, tid);
        SYNC_ST(8, false);
        ld_grp<8, false>(rA, rW, h0h + 64, h0l + 64, PH, 0, row0, tid);
        comp_grp<8>(a0, a1, sA, smem + 16384, smem + 24576, aoff, boff0, boff1);
        SYNC_ST(8, false);
        ld_grp<8, false>(rA, rW, h1h, h1l, PH, 0, row0, tid);
        comp_grp<8>(a0, a1, sA, smem + 20480, smem + 28672, aoff, boff0, boff1);
        SYNC_ST(8, false);
        ld_grp<8, false>(rA, rW, h1h + 64, h1l + 64, PH, 0, row0, tid);
        comp_grp<8>(a0, a1, sA, smem + 0, smem + 8192, aoff, boff0, boff1);
        SYNC_ST(8, false);
        comp_grp<8>(a0, a1, sA, smem + 4096, smem + 12288, aoff, boff0, boff1);
        epilogue(a0, a1, c0r, bdp, row0, by, tid, wm, g_, hidT,
                 g_h0hi[par ^ 1], g_h0lo[par ^ 1], nullptr, hbuf);
      }
    }
    bt += 16; gbar(bx, bt);
    {  // L1: h1old @ Whh1 (lo streamed) first, then h0new @ Wih1 (lo streamed)
      const uint32_t *nh = g_h0hi[par ^ 1], *nl = g_h0lo[par ^ 1];
      float a0[4] = {}, a1[4] = {};
      ld_grp<8, true>(rA, rW, h1h, h1l, PH, hh1lo, row0, tid);
      SYNC_ST(8, true);
      ld_grp<8, true>(rA, rW, h1h + 64, h1l + 64, PH, hh1lo + 64, row0, tid);
      comp_grp<8>(a0, a1, sA, smem + 40960, sWst, aoff, boff0, boff1);
      SYNC_ST(8, true);
      ld_grp<8, true>(rA, rW, nh, nl, PH, ih1lo, row0, tid);
      comp_grp<8>(a0, a1, sA, smem + 45056, sWst, aoff, boff0, boff1);
      SYNC_ST(8, true);
      ld_grp<8, true>(rA, rW, nh + 64, nl + 64, PH, ih1lo + 64, row0, tid);
      comp_grp<8>(a0, a1, sA, smem + 32768, sWst, aoff, boff0, boff1);
      SYNC_ST(8, true);
      comp_grp<8>(a0, a1, sA, smem + 36864, sWst, aoff, boff0, boff1);
      epilogue(a0, a1, c1r, bd1, row0, by, tid, wm, g_, hidT,
               g_h1hi[par ^ 1], g_h1lo[par ^ 1],
               g_h1s + (size_t)s * BSZ * HSZ, hbuf);
    }
    bt += 16; gbar(bx, bt);
    par ^= 1;
  }
}

// ---------------- final projection ----------------
__global__ __launch_bounds__(256) void out_proj(const float* __restrict__ Wout,
                                                const float* __restrict__ bout,
                                                float* __restrict__ out) {
  __shared__ float hs[32][65];
  __shared__ float wsT[64][36];
  int tid = threadIdx.x;
  int b0 = blockIdx.x * 32, s = blockIdx.y;
  int bloc = tid & 31, f0 = (tid >> 5) * 4;
  float acc[4] = {0.f, 0.f, 0.f, 0.f};
  const float* hsrc = g_h1s + (size_t)s * BSZ * HSZ;
  for (int k0 = 0; k0 < HSZ; k0 += 64) {
    __syncthreads();
#pragma unroll
    for (int qq = 0; qq < 2; ++qq) {
      int idx = tid + qq * 256, row = idx >> 4, kq = idx & 15;
      float4 v = *(const float4*)(hsrc + (size_t)(b0 + row) * HSZ + k0 + kq * 4);
      hs[row][kq * 4 + 0] = v.x; hs[row][kq * 4 + 1] = v.y;
      hs[row][kq * 4 + 2] = v.z; hs[row][kq * 4 + 3] = v.w;
      float4 w = *(const float4*)(Wout + (size_t)row * HSZ + k0 + kq * 4);
      wsT[kq * 4 + 0][row] = w.x; wsT[kq * 4 + 1][row] = w.y;
      wsT[kq * 4 + 2][row] = w.z; wsT[kq * 4 + 3][row] = w.w;
    }
    __syncthreads();
#pragma unroll 8
    for (int kk = 0; kk < 64; ++kk) {
      float hv = hs[bloc][kk];
      float4 w = *(const float4*)&wsT[kk][f0];
      acc[0] += hv * w.x; acc[1] += hv * w.y;
      acc[2] += hv * w.z; acc[3] += hv * w.w;
    }
  }
  float* op = out + (size_t)(b0 + bloc) * TOUT * FSZ + s * FSZ + f0;
  op[0] = acc[0] + bout[f0 + 0];
  op[1] = acc[1] + bout[f0 + 1];
  op[2] = acc[2] + bout[f0 + 2];
  op[3] = acc[3] + bout[f0 + 3];
}

// ---------------- host ----------------
extern "C" void kernel_launch(void* const* d_in, const int* in_sizes, int n_in,
                              void* d_out, int out_size) {
  (void)in_sizes; (void)n_in; (void)out_size;
  const float* x     = (const float*)d_in[0];
  const float* eWih0 = (const float*)d_in[1];
  const float* eWhh0 = (const float*)d_in[2];
  const float* eb0   = (const float*)d_in[3];
  const float* eWih1 = (const float*)d_in[4];
  const float* eWhh1 = (const float*)d_in[5];
  const float* eb1   = (const float*)d_in[6];
  const float* dWih0 = (const float*)d_in[7];
  const float* dWhh0 = (const float*)d_in[8];
  const float* db0   = (const float*)d_in[9];
  const float* dWih1 = (const float*)d_in[10];
  const float* dWhh1 = (const float*)d_in[11];
  const float* db1   = (const float*)d_in[12];
  const float* dWout = (const float*)d_in[13];
  const float* dbout = (const float*)d_in[14];

  void* p;
  cudaGetSymbolAddress(&p, g_Wp);      float* Wp = (float*)p;
  cudaGetSymbolAddress(&p, g_eWih0h);  uint32_t* eWih0h = (uint32_t*)p;
  cudaGetSymbolAddress(&p, g_eWih0l);  uint32_t* eWih0l = (uint32_t*)p;
  cudaGetSymbolAddress(&p, g_eWhh0h);  uint32_t* eWhh0h = (uint32_t*)p;
  cudaGetSymbolAddress(&p, g_eWhh0l);  uint32_t* eWhh0l = (uint32_t*)p;
  cudaGetSymbolAddress(&p, g_eWih1h);  uint32_t* eWih1h = (uint32_t*)p;
  cudaGetSymbolAddress(&p, g_eWih1l);  uint32_t* eWih1l = (uint32_t*)p;
  cudaGetSymbolAddress(&p, g_eWhh1h);  uint32_t* eWhh1h = (uint32_t*)p;
  cudaGetSymbolAddress(&p, g_eWhh1l);  uint32_t* eWhh1l = (uint32_t*)p;
  cudaGetSymbolAddress(&p, g_dWih0h);  uint32_t* dWih0h = (uint32_t*)p;
  cudaGetSymbolAddress(&p, g_dWih0l);  uint32_t* dWih0l = (uint32_t*)p;
  cudaGetSymbolAddress(&p, g_dWhh0h);  uint32_t* dWhh0h = (uint32_t*)p;
  cudaGetSymbolAddress(&p, g_dWhh0l);  uint32_t* dWhh0l = (uint32_t*)p;
  cudaGetSymbolAddress(&p, g_dWih1h);  uint32_t* dWih1h = (uint32_t*)p;
  cudaGetSymbolAddress(&p, g_dWih1l);  uint32_t* dWih1l = (uint32_t*)p;
  cudaGetSymbolAddress(&p, g_dWhh1h);  uint32_t* dWhh1h = (uint32_t*)p;
  cudaGetSymbolAddress(&p, g_dWhh1l);  uint32_t* dWhh1l = (uint32_t*)p;
  cudaGetSymbolAddress(&p, g_Wph);     uint32_t* Wph = (uint32_t*)p;
  cudaGetSymbolAddress(&p, g_Wpl);     uint32_t* Wpl = (uint32_t*)p;

  cudaFuncSetAttribute(lstm_persist, cudaFuncAttributeMaxDynamicSharedMemorySize,
                       SMW * 4);

  zero_init_kernel<<<(BSZ * PH) / 256, 256>>>();
  wp_kernel<<<4 * HSZ, 256>>>(dWih0, dWout);
  bp_kernel<<<(4 * HSZ) / 256, 256>>>(dWih0, db0, dbout);
  pack_x<<<(BSZ * TIN * PX) / 256, 256>>>(x);
  pack_w<<<(1024 * 16) / 256, 256>>>(eWih0, 32, eWih0h, eWih0l);
  pack_w<<<(1024 * 128) / 256, 256>>>(eWhh0, 256, eWhh0h, eWhh0l);
  pack_w<<<(1024 * 128) / 256, 256>>>(eWih1, 256, eWih1h, eWih1l);
  pack_w<<<(1024 * 128) / 256, 256>>>(eWhh1, 256, eWhh1h, eWhh1l);
  pack_w<<<(1024 * 16) / 256, 256>>>(dWih0, 32, dWih0h, dWih0l);
  pack_w<<<(1024 * 128) / 256, 256>>>(dWhh0, 256, dWhh0h, dWhh0l);
  pack_w<<<(1024 * 128) / 256, 256>>>(dWih1, 256, dWih1h, dWih1l);
  pack_w<<<(1024 * 128) / 256, 256>>>(dWhh1, 256, dWhh1h, dWhh1l);
  pack_w<<<(1024 * 128) / 256, 256>>>(Wp, 256, Wph, Wpl);

  lstm_persist<<<NCTA, 256, SMW * 4>>>(eb0, eb1, db0, db1);
  out_proj<<<dim3(BSZ / 32, TOUT), 256>>>(dWout, dbout, (float*)d_out);
}

// round 14
// speedup vs baseline: 2.1295x; 1.0121x over previous
#include <cuda_runtime.h>
#include <cuda_bf16.h>
#include <math.h>
#include <stdint.h>

#define BSZ 256
#define HSZ 256
#define TIN 336
#define TOUT 96
#define FSZ 32
#define PH 128
#define PX 16
#define NCTA 128
#define NTHR 512
#define SMW 57344

__device__ uint32_t g_h0hi[2][BSZ * PH], g_h0lo[2][BSZ * PH];
__device__ uint32_t g_h1hi[2][BSZ * PH], g_h1lo[2][BSZ * PH];
__device__ uint32_t g_xhi[BSZ * TIN * PX], g_xlo[BSZ * TIN * PX];
__device__ float g_Wp[4 * HSZ * HSZ], g_bp[4 * HSZ];
__device__ float g_h1s[(size_t)TOUT * BSZ * HSZ];
__device__ unsigned g_gbar[8 * 32];

__device__ uint32_t g_eWih0h[1024 * 16],  g_eWih0l[1024 * 16];
__device__ uint32_t g_eWhh0h[1024 * 128], g_eWhh0l[1024 * 128];
__device__ uint32_t g_eWih1h[1024 * 128], g_eWih1l[1024 * 128];
__device__ uint32_t g_eWhh1h[1024 * 128], g_eWhh1l[1024 * 128];
__device__ uint32_t g_dWih0h[1024 * 16],  g_dWih0l[1024 * 16];
__device__ uint32_t g_dWhh0h[1024 * 128], g_dWhh0l[1024 * 128];
__device__ uint32_t g_dWih1h[1024 * 128], g_dWih1l[1024 * 128];
__device__ uint32_t g_dWhh1h[1024 * 128], g_dWhh1l[1024 * 128];
__device__ uint32_t g_Wph[1024 * 128],    g_Wpl[1024 * 128];

__device__ __forceinline__ int j2lp(int j) { return ((j & 1) << 2) | (j >> 1); }

__device__ __forceinline__ void split2(float v0, float v1, uint32_t& hi, uint32_t& lo) {
  __nv_bfloat16 h0 = __float2bfloat16_rn(v0), h1 = __float2bfloat16_rn(v1);
  __nv_bfloat16 l0 = __float2bfloat16_rn(v0 - __bfloat162float(h0));
  __nv_bfloat16 l1 = __float2bfloat16_rn(v1 - __bfloat162float(h1));
  __nv_bfloat162 ph = __nv_bfloat162(h0, h1), pl = __nv_bfloat162(l0, l1);
  hi = *(uint32_t*)&ph;
  lo = *(uint32_t*)&pl;
}

#define MMA_BF16(C, a0, a1, a2, a3, b0, b1)                                   \
  asm volatile(                                                               \
      "mma.sync.aligned.m16n8k16.row.col.f32.bf16.bf16.f32 "                  \
      "{%0,%1,%2,%3},{%4,%5,%6,%7},{%8,%9},{%0,%1,%2,%3};"                    \
      : "+f"(C[0]), "+f"(C[1]), "+f"(C[2]), "+f"(C[3])                        \
      : "r"(a0), "r"(a1), "r"(a2), "r"(a3), "r"(b0), "r"(b1))

#define LDG_CG2(v, p)                                                         \
  asm volatile("ld.global.cg.v2.u32 {%0,%1},[%2];"                            \
               : "=r"((v).x), "=r"((v).y) : "l"(p))

// ---------------- init / preprocess ----------------
__global__ void zero_init_kernel() {
  int i = blockIdx.x * blockDim.x + threadIdx.x;
  g_h0hi[0][i] = 0u; g_h0lo[0][i] = 0u;
  g_h1hi[0][i] = 0u; g_h1lo[0][i] = 0u;
  if (i < 256) g_gbar[i] = 0u;
}

__global__ void wp_kernel(const float* __restrict__ Wih0, const float* __restrict__ Wout) {
  __shared__ float wr[FSZ];
  int c = blockIdx.x;
  if (threadIdx.x < FSZ) wr[threadIdx.x] = Wih0[c * FSZ + threadIdx.x];
  __syncthreads();
  int k = threadIdx.x;
  float acc = 0.f;
#pragma unroll
  for (int f = 0; f < FSZ; ++f) acc += wr[f] * Wout[f * HSZ + k];
  g_Wp[c * HSZ + k] = acc;
}

__global__ void bp_kernel(const float* __restrict__ Wih0, const float* __restrict__ b0,
                          const float* __restrict__ bout) {
  int c = blockIdx.x * blockDim.x + threadIdx.x;
  float acc = b0[c];
#pragma unroll
  for (int f = 0; f < FSZ; ++f) acc += Wih0[c * FSZ + f] * bout[f];
  g_bp[c] = acc;
}

// gate-interleaved packing: each mma thread's accumulators hold {i,f,g,o} of one hid
__global__ void pack_w(const float* __restrict__ W, int K,
                       uint32_t* __restrict__ ohi, uint32_t* __restrict__ olo) {
  int P = K >> 1;
  int idx = blockIdx.x * 256 + threadIdx.x;
  if (idx >= 1024 * P) return;
  int pr = idx / P, w = idx % P;
  int n = pr & 63, by = pr >> 6;
  int eps = (n >> 3) & 1, qq = (n >> 1) & 3, dlt = n & 1;
  int gate = 2 * eps + dlt;
  int hid = ((n >> 4) << 2) + qq;
  int r = gate * 256 + by * 16 + hid;
  int cch = w >> 3, j = w & 7;
  int k0 = cch * 16 + 2 * j2lp(j);
  split2(W[r * K + k0], W[r * K + k0 + 1], ohi[idx], olo[idx]);
}

__global__ void pack_x(const float* __restrict__ x) {
  int idx = blockIdx.x * 256 + threadIdx.x;
  int w = idx & (PX - 1), bt = idx >> 4;
  int cch = w >> 3, j = w & 7;
  int k0 = cch * 16 + 2 * j2lp(j);
  const float* src = x + (size_t)bt * FSZ + k0;
  split2(src[0], src[1], g_xhi[idx], g_xlo[idx]);
}

// ---------------- persistent building blocks ----------------
__device__ __forceinline__ void gbar(int grp, unsigned target) {
  __syncthreads();
  __threadfence();
  if (threadIdx.x == 0) {
    unsigned old = atomicAdd(&g_gbar[grp * 32], 1u);
    if (old + 1u < target) {
      volatile unsigned* p = &g_gbar[grp * 32];
      while (*p < target) {}
    }
  }
  __syncthreads();
}

__device__ __forceinline__ void ld_res(uint32_t* dst, const uint32_t* src,
                                       int P, int by, int tid) {
  const uint32_t* s = src + (size_t)(by * 64) * P;
  for (int idx = tid * 2; idx < 64 * P; idx += 1024) {
    int rw = idx / P, w = idx - rw * P;
    int c = w >> 3, j = w & 7;
    uint2 v = *(const uint2*)(s + (size_t)rw * P + w);
    *(uint2*)&dst[c * 512 + rw * 8 + j] = v;
  }
}

template <int GC, bool SW>
__device__ __forceinline__ void ld_grp(uint2* rA, uint2* rW,
    const uint32_t* __restrict__ ahi, const uint32_t* __restrict__ alo,
    int lda, const uint32_t* __restrict__ gwl, int row0, int tid) {
  constexpr int ITS = (GC + 3) / 4;
#pragma unroll
  for (int it = 0; it < ITS; ++it) {
    int idx = tid * 2 + it * 1024;
    if (GC >= 4 || idx < GC * 256) {
      int rw = (idx & 255) >> 3, j = idx & 7, c = idx >> 8;
      size_t go = (size_t)(row0 + rw) * lda + (c << 3) + j;
      LDG_CG2(rA[2 * it], ahi + go);
      LDG_CG2(rA[2 * it + 1], alo + go);
    }
  }
  if (SW) {
#pragma unroll
    for (int it = 0; it < (GC + 1) / 2; ++it) {
      int idx = tid * 2 + it * 1024;
      int rw = (idx & 511) >> 3, j = idx & 7, c = idx >> 9;
      LDG_CG2(rW[it], gwl + rw * PH + (c << 3) + j);
    }
  }
}

template <int GC, bool SW>
__device__ __forceinline__ void st_grp(const uint2* rA, const uint2* rW,
                                       uint32_t* sA, uint32_t* sWst, int tid) {
  constexpr int ITS = (GC + 3) / 4;
#pragma unroll
  for (int it = 0; it < ITS; ++it) {
    int idx = tid * 2 + it * 1024;
    if (GC >= 4 || idx < GC * 256) {
      *(uint2*)&sA[idx] = rA[2 * it];
      *(uint2*)&sA[2048 + idx] = rA[2 * it + 1];
    }
  }
  if (SW) {
#pragma unroll
    for (int it = 0; it < (GC + 1) / 2; ++it)
      *(uint2*)&sWst[tid * 2 + it * 1024] = rW[it];
  }
}

// k-split: warps with ks=0 take the first half of each group's chunks, ks=1 the rest
template <int GC>
__device__ __forceinline__ void comp_grp(float* a0, float* a1,
    const uint32_t* sA, const uint32_t* swh, const uint32_t* swl,
    int aoff, int boff0, int boff1, int ks) {
  int cb = ks * (GC >> 1);
#pragma unroll
  for (int ci = 0; ci < (GC >> 1); ++ci) {
    int c = cb + ci;
    const uint32_t* bAh = sA + (c << 8);
    const uint32_t* bAl = bAh + 2048;
    const uint32_t* bWh = swh + (c << 9);
    const uint32_t* bWl = swl + (c << 9);
    uint2 Ah0 = *(const uint2*)(bAh + aoff), Ah1 = *(const uint2*)(bAh + aoff + 64);
    uint2 Al0 = *(const uint2*)(bAl + aoff), Al1 = *(const uint2*)(bAl + aoff + 64);
    uint2 Bh0 = *(const uint2*)(bWh + boff0), Bl0 = *(const uint2*)(bWl + boff0);
    uint2 Bh1 = *(const uint2*)(bWh + boff1), Bl1 = *(const uint2*)(bWl + boff1);
    MMA_BF16(a0, Ah0.x, Ah1.x, Ah0.y, Ah1.y, Bh0.x, Bh0.y);
    MMA_BF16(a0, Ah0.x, Ah1.x, Ah0.y, Ah1.y, Bl0.x, Bl0.y);
    MMA_BF16(a0, Al0.x, Al1.x, Al0.y, Al1.y, Bh0.x, Bh0.y);
    MMA_BF16(a1, Ah0.x, Ah1.x, Ah0.y, Ah1.y, Bh1.x, Bh1.y);
    MMA_BF16(a1, Ah0.x, Ah1.x, Ah0.y, Ah1.y, Bl1.x, Bl1.y);
    MMA_BF16(a1, Al0.x, Al1.x, Al0.y, Al1.y, Bh1.x, Bh1.y);
  }
}

// partial-reduce across k-split pair, then register-resident pointwise
__device__ __forceinline__ void epilogue(
    float* a0, float* a1, float* creg, float4 bu,
    int row0, int by, int tid, int ks, int wm, int g_, int hidT,
    uint32_t* __restrict__ outHi, uint32_t* __restrict__ outLo,
    float* __restrict__ outF, float* sbase) {
  float* psum = sbase;
  float* hbuf = sbase + 2048;
  __syncthreads();
  if (ks) {
    float4* p = (float4*)(psum + (tid - 256) * 8);
    p[0] = make_float4(a0[0], a0[1], a0[2], a0[3]);
    p[1] = make_float4(a1[0], a1[1], a1[2], a1[3]);
  }
  __syncthreads();
  if (!ks) {
    const float4* p = (const float4*)(psum + tid * 8);
    float4 p0 = p[0], p1 = p[1];
    a0[0] += p0.x; a0[1] += p0.y; a0[2] += p0.z; a0[3] += p0.w;
    a1[0] += p1.x; a1[1] += p1.y; a1[2] += p1.z; a1[3] += p1.w;
#pragma unroll
    for (int uu = 0; uu < 2; ++uu) {
      int row = wm + g_ + 8 * uu;
      float gi = (uu ? a0[2] : a0[0]) + bu.x;
      float gf = (uu ? a0[3] : a0[1]) + bu.y;
      float gg = (uu ? a1[2] : a1[0]) + bu.z;
      float go = (uu ? a1[3] : a1[1]) + bu.w;
      float si = 1.f / (1.f + expf(-gi));
      float sf = 1.f / (1.f + expf(-gf));
      float so = 1.f / (1.f + expf(-go));
      float cn = sf * creg[uu] + si * tanhf(gg);
      float hn = so * tanhf(cn);
      creg[uu] = cn;
      hbuf[row * 17 + hidT] = hn;
      if (outF) outF[(size_t)(row0 + row) * HSZ + by * 16 + hidT] = hn;
    }
  }
  __syncthreads();
  if (tid < 256) {
    int pr = tid >> 3, jj = tid & 7, lp = j2lp(jj);
    uint32_t hi, lo;
    split2(hbuf[pr * 17 + 2 * lp], hbuf[pr * 17 + 2 * lp + 1], hi, lo);
    size_t o = (size_t)(row0 + pr) * PH + by * 8 + jj;
    outHi[o] = hi;
    outLo[o] = lo;
  }
}

__device__ __forceinline__ float4 bias4(const float* b, int gh) {
  return make_float4(b[gh], b[HSZ + gh], b[2 * HSZ + gh], b[3 * HSZ + gh]);
}

#define SYNC_ST(GC, SW)                                                       \
  __syncthreads();                                                            \
  st_grp<GC, SW>(rA, rW, sA, sWst, tid);                                      \
  __syncthreads()

// ---------------- persistent kernel ----------------
__global__ __launch_bounds__(NTHR) void lstm_persist(
    const float* __restrict__ eb0, const float* __restrict__ eb1,
    const float* __restrict__ db0, const float* __restrict__ db1) {
  extern __shared__ uint32_t smem[];
  int tid = threadIdx.x;
  int bx = blockIdx.x & 7, by = blockIdx.x >> 3;
  int row0 = bx * 32;
  int lane = tid & 31, wid = tid >> 5, g_ = lane >> 2, q = lane & 3;
  int ks = wid >> 3, wpos = wid & 7;
  int wm = (wpos & 1) * 16, wn = (wpos >> 1) * 16;
  int hidT = (wn >> 2) + q;
  int aoff = (wm + g_) * 8 + 2 * q;
  int boff0 = (wn + g_) * 8 + 2 * q, boff1 = (wn + 8 + g_) * 8 + 2 * q;
  uint32_t* sA = smem + 49152;
  uint32_t* sWst = smem + 53248;
  float* sbase = (float*)sA;
  int gh = by * 16 + hidT;
  float c0r[2] = {0.f, 0.f}, c1r[2] = {0.f, 0.f};
  unsigned bt = 0;
  int par = 0;
  uint2 rA[4], rW[4];

  // ---- encoder ----
  ld_res(smem + 0,     g_eWhh0h, 128, by, tid);
  ld_res(smem + 8192,  g_eWhh0l, 128, by, tid);
  ld_res(smem + 16384, g_eWih1h, 128, by, tid);
  ld_res(smem + 24576, g_eWih1l, 128, by, tid);
  ld_res(smem + 32768, g_eWhh1h, 128, by, tid);
  ld_res(smem + 40960, g_eWhh1l, 128, by, tid);
  ld_res(sWst,         g_eWih0h, 16, by, tid);
  ld_res(sWst + 1024,  g_eWih0l, 16, by, tid);
  float4 be0 = bias4(eb0, gh), be1 = bias4(eb1, gh);

  for (int t = 0; t < TIN; ++t) {
    const uint32_t *h0h = g_h0hi[par], *h0l = g_h0lo[par];
    const uint32_t *h1h = g_h1hi[par], *h1l = g_h1lo[par];
    {  // L0: x @ Wih0 + h0old @ Whh0
      float a0[4] = {}, a1[4] = {};
      ld_grp<2, false>(rA, rW, g_xhi + (size_t)t * PX, g_xlo + (size_t)t * PX,
                       TIN * PX, 0, row0, tid);
      SYNC_ST(2, false);
      ld_grp<8, false>(rA, rW, h0h, h0l, PH, 0, row0, tid);
      comp_grp<2>(a0, a1, sA, sWst, sWst + 1024, aoff, boff0, boff1, ks);
      SYNC_ST(8, false);
      ld_grp<8, false>(rA, rW, h0h + 64, h0l + 64, PH, 0, row0, tid);
      comp_grp<8>(a0, a1, sA, smem + 0, smem + 8192, aoff, boff0, boff1, ks);
      SYNC_ST(8, false);
      comp_grp<8>(a0, a1, sA, smem + 4096, smem + 12288, aoff, boff0, boff1, ks);
      epilogue(a0, a1, c0r, be0, row0, by, tid, ks, wm, g_, hidT,
               g_h0hi[par ^ 1], g_h0lo[par ^ 1], nullptr, sbase);
    }
    bt += 16; gbar(bx, bt);
    {  // L1: h1old @ Whh1, then h0new @ Wih1
      const uint32_t *nh = g_h0hi[par ^ 1], *nl = g_h0lo[par ^ 1];
      float a0[4] = {}, a1[4] = {};
      ld_grp<8, false>(rA, rW, h1h, h1l, PH, 0, row0, tid);
      SYNC_ST(8, false);
      ld_grp<8, false>(rA, rW, h1h + 64, h1l + 64, PH, 0, row0, tid);
      comp_grp<8>(a0, a1, sA, smem + 32768, smem + 40960, aoff, boff0, boff1, ks);
      SYNC_ST(8, false);
      ld_grp<8, false>(rA, rW, nh, nl, PH, 0, row0, tid);
      comp_grp<8>(a0, a1, sA, smem + 36864, smem + 45056, aoff, boff0, boff1, ks);
      SYNC_ST(8, false);
      ld_grp<8, false>(rA, rW, nh + 64, nl + 64, PH, 0, row0, tid);
      comp_grp<8>(a0, a1, sA, smem + 16384, smem + 24576, aoff, boff0, boff1, ks);
      SYNC_ST(8, false);
      comp_grp<8>(a0, a1, sA, smem + 20480, smem + 28672, aoff, boff0, boff1, ks);
      epilogue(a0, a1, c1r, be1, row0, by, tid, ks, wm, g_, hidT,
               g_h1hi[par ^ 1], g_h1lo[par ^ 1], nullptr, sbase);
    }
    par ^= 1;
  }

  // ---- decoder ----
  ld_res(smem + 0,     g_Wph,    128, by, tid);
  ld_res(smem + 8192,  g_Wpl,    128, by, tid);
  ld_res(smem + 16384, g_dWhh0h, 128, by, tid);
  ld_res(smem + 24576, g_dWhh0l, 128, by, tid);
  ld_res(smem + 32768, g_dWih1h, 128, by, tid);
  ld_res(smem + 40960, g_dWhh1h, 128, by, tid);
  ld_res(sWst,         g_dWih0h, 16, by, tid);
  ld_res(sWst + 1024,  g_dWih0l, 16, by, tid);
  __syncthreads();
  const uint32_t* ih1lo = g_dWih1l + (size_t)by * 64 * PH;
  const uint32_t* hh1lo = g_dWhh1l + (size_t)by * 64 * PH;
  float4 bd0 = bias4(db0, gh), bdp = bias4(g_bp, gh), bd1 = bias4(db1, gh);

  for (int s = 0; s < TOUT; ++s) {
    const uint32_t *h0h = g_h0hi[par], *h0l = g_h0lo[par];
    const uint32_t *h1h = g_h1hi[par], *h1l = g_h1lo[par];
    {  // L0
      float a0[4] = {}, a1[4] = {};
      if (s == 0) {
        ld_grp<2, false>(rA, rW, g_xhi + (size_t)(TIN - 1) * PX,
                         g_xlo + (size_t)(TIN - 1) * PX, TIN * PX, 0, row0, tid);
        SYNC_ST(2, false);
        ld_grp<8, false>(rA, rW, h0h, h0l, PH, 0, row0, tid);
        comp_grp<2>(a0, a1, sA, sWst, sWst + 1024, aoff, boff0, boff1, ks);
        SYNC_ST(8, false);
        ld_grp<8, false>(rA, rW, h0h + 64, h0l + 64, PH, 0, row0, tid);
        comp_grp<8>(a0, a1, sA, smem + 16384, smem + 24576, aoff, boff0, boff1, ks);
        SYNC_ST(8, false);
        comp_grp<8>(a0, a1, sA, smem + 20480, smem + 28672, aoff, boff0, boff1, ks);
        epilogue(a0, a1, c0r, bd0, row0, by, tid, ks, wm, g_, hidT,
                 g_h0hi[par ^ 1], g_h0lo[par ^ 1], nullptr, sbase);
      } else {  // h0old @ Whh0 first, then h1 @ Wp
        ld_grp<8, false>(rA, rW, h0h, h0l, PH, 0, row0, tid);
        SYNC_ST(8, false);
        ld_grp<8, false>(rA, rW, h0h + 64, h0l + 64, PH, 0, row0, tid);
        comp_grp<8>(a0, a1, sA, smem + 16384, smem + 24576, aoff, boff0, boff1, ks);
        SYNC_ST(8, false);
        ld_grp<8, false>(rA, rW, h1h, h1l, PH, 0, row0, tid);
        comp_grp<8>(a0, a1, sA, smem + 20480, smem + 28672, aoff, boff0, boff1, ks);
        SYNC_ST(8, false);
        ld_grp<8, false>(rA, rW, h1h + 64, h1l + 64, PH, 0, row0, tid);
        comp_grp<8>(a0, a1, sA, smem + 0, smem + 8192, aoff, boff0, boff1, ks);
        SYNC_ST(8, false);
        comp_grp<8>(a0, a1, sA, smem + 4096, smem + 12288, aoff, boff0, boff1, ks);
        epilogue(a0, a1, c0r, bdp, row0, by, tid, ks, wm, g_, hidT,
                 g_h0hi[par ^ 1], g_h0lo[par ^ 1], nullptr, sbase);
      }
    }
    bt += 16; gbar(bx, bt);
    {  // L1: h1old @ Whh1 (lo streamed), then h0new @ Wih1 (lo streamed)
      const uint32_t *nh = g_h0hi[par ^ 1], *nl = g_h0lo[par ^ 1];
      float a0[4] = {}, a1[4] = {};
      ld_grp<8, true>(rA, rW, h1h, h1l, PH, hh1lo, row0, tid);
      SYNC_ST(8, true);
      ld_grp<8, true>(rA, rW, h1h + 64, h1l + 64, PH, hh1lo + 64, row0, tid);
      comp_grp<8>(a0, a1, sA, smem + 40960, sWst, aoff, boff0, boff1, ks);
      SYNC_ST(8, true);
      ld_grp<8, true>(rA, rW, nh, nl, PH, ih1lo, row0, tid);
      comp_grp<8>(a0, a1, sA, smem + 45056, sWst, aoff, boff0, boff1, ks);
      SYNC_ST(8, true);
      ld_grp<8, true>(rA, rW, nh + 64, nl + 64, PH, ih1lo + 64, row0, tid);
      comp_grp<8>(a0, a1, sA, smem + 32768, sWst, aoff, boff0, boff1, ks);
      SYNC_ST(8, true);
      comp_grp<8>(a0, a1, sA, smem + 36864, sWst, aoff, boff0, boff1, ks);
      epilogue(a0, a1, c1r, bd1, row0, by, tid, ks, wm, g_, hidT,
               g_h1hi[par ^ 1], g_h1lo[par ^ 1],
               g_h1s + (size_t)s * BSZ * HSZ, sbase);
    }
    bt += 16; gbar(bx, bt);
    par ^= 1;
  }
}

// ---------------- final projection ----------------
__global__ __launch_bounds__(256) void out_proj(const float* __restrict__ Wout,
                                                const float* __restrict__ bout,
                                                float* __restrict__ out) {
  __shared__ float hs[32][65];
  __shared__ float wsT[64][36];
  int tid = threadIdx.x;
  int b0 = blockIdx.x * 32, s = blockIdx.y;
  int bloc = tid & 31, f0 = (tid >> 5) * 4;
  float acc[4] = {0.f, 0.f, 0.f, 0.f};
  const float* hsrc = g_h1s + (size_t)s * BSZ * HSZ;
  for (int k0 = 0; k0 < HSZ; k0 += 64) {
    __syncthreads();
#pragma unroll
    for (int qq = 0; qq < 2; ++qq) {
      int idx = tid + qq * 256, row = idx >> 4, kq = idx & 15;
      float4 v = *(const float4*)(hsrc + (size_t)(b0 + row) * HSZ + k0 + kq * 4);
      hs[row][kq * 4 + 0] = v.x; hs[row][kq * 4 + 1] = v.y;
      hs[row][kq * 4 + 2] = v.z; hs[row][kq * 4 + 3] = v.w;
      float4 w = *(const float4*)(Wout + (size_t)row * HSZ + k0 + kq * 4);
      wsT[kq * 4 + 0][row] = w.x; wsT[kq * 4 + 1][row] = w.y;
      wsT[kq * 4 + 2][row] = w.z; wsT[kq * 4 + 3][row] = w.w;
    }
    __syncthreads();
#pragma unroll 8
    for (int kk = 0; kk < 64; ++kk) {
      float hv = hs[bloc][kk];
      float4 w = *(const float4*)&wsT[kk][f0];
      acc[0] += hv * w.x; acc[1] += hv * w.y;
      acc[2] += hv * w.z; acc[3] += hv * w.w;
    }
  }
  float* op = out + (size_t)(b0 + bloc) * TOUT * FSZ + s * FSZ + f0;
  op[0] = acc[0] + bout[f0 + 0];
  op[1] = acc[1] + bout[f0 + 1];
  op[2] = acc[2] + bout[f0 + 2];
  op[3] = acc[3] + bout[f0 + 3];
}

// ---------------- host ----------------
extern "C" void kernel_launch(void* const* d_in, const int* in_sizes, int n_in,
                              void* d_out, int out_size) {
  (void)in_sizes; (void)n_in; (void)out_size;
  const float* x     = (const float*)d_in[0];
  const float* eWih0 = (const float*)d_in[1];
  const float* eWhh0 = (const float*)d_in[2];
  const float* eb0   = (const float*)d_in[3];
  const float* eWih1 = (const float*)d_in[4];
  const float* eWhh1 = (const float*)d_in[5];
  const float* eb1   = (const float*)d_in[6];
  const float* dWih0 = (const float*)d_in[7];
  const float* dWhh0 = (const float*)d_in[8];
  const float* db0   = (const float*)d_in[9];
  const float* dWih1 = (const float*)d_in[10];
  const float* dWhh1 = (const float*)d_in[11];
  const float* db1   = (const float*)d_in[12];
  const float* dWout = (const float*)d_in[13];
  const float* dbout = (const float*)d_in[14];

  void* p;
  cudaGetSymbolAddress(&p, g_Wp);      float* Wp = (float*)p;
  cudaGetSymbolAddress(&p, g_eWih0h);  uint32_t* eWih0h = (uint32_t*)p;
  cudaGetSymbolAddress(&p, g_eWih0l);  uint32_t* eWih0l = (uint32_t*)p;
  cudaGetSymbolAddress(&p, g_eWhh0h);  uint32_t* eWhh0h = (uint32_t*)p;
  cudaGetSymbolAddress(&p, g_eWhh0l);  uint32_t* eWhh0l = (uint32_t*)p;
  cudaGetSymbolAddress(&p, g_eWih1h);  uint32_t* eWih1h = (uint32_t*)p;
  cudaGetSymbolAddress(&p, g_eWih1l);  uint32_t* eWih1l = (uint32_t*)p;
  cudaGetSymbolAddress(&p, g_eWhh1h);  uint32_t* eWhh1h = (uint32_t*)p;
  cudaGetSymbolAddress(&p, g_eWhh1l);  uint32_t* eWhh1l = (uint32_t*)p;
  cudaGetSymbolAddress(&p, g_dWih0h);  uint32_t* dWih0h = (uint32_t*)p;
  cudaGetSymbolAddress(&p, g_dWih0l);  uint32_t* dWih0l = (uint32_t*)p;
  cudaGetSymbolAddress(&p, g_dWhh0h);  uint32_t* dWhh0h = (uint32_t*)p;
  cudaGetSymbolAddress(&p, g_dWhh0l);  uint32_t* dWhh0l = (uint32_t*)p;
  cudaGetSymbolAddress(&p, g_dWih1h);  uint32_t* dWih1h = (uint32_t*)p;
  cudaGetSymbolAddress(&p, g_dWih1l);  uint32_t* dWih1l = (uint32_t*)p;
  cudaGetSymbolAddress(&p, g_dWhh1h);  uint32_t* dWhh1h = (uint32_t*)p;
  cudaGetSymbolAddress(&p, g_dWhh1l);  uint32_t* dWhh1l = (uint32_t*)p;
  cudaGetSymbolAddress(&p, g_Wph);     uint32_t* Wph = (uint32_t*)p;
  cudaGetSymbolAddress(&p, g_Wpl);     uint32_t* Wpl = (uint32_t*)p;

  cudaFuncSetAttribute(lstm_persist, cudaFuncAttributeMaxDynamicSharedMemorySize,
                       SMW * 4);

  zero_init_kernel<<<(BSZ * PH) / 256, 256>>>();
  wp_kernel<<<4 * HSZ, 256>>>(dWih0, dWout);
  bp_kernel<<<(4 * HSZ) / 256, 256>>>(dWih0, db0, dbout);
  pack_x<<<(BSZ * TIN * PX) / 256, 256>>>(x);
  pack_w<<<(1024 * 16) / 256, 256>>>(eWih0, 32, eWih0h, eWih0l);
  pack_w<<<(1024 * 128) / 256, 256>>>(eWhh0, 256, eWhh0h, eWhh0l);
  pack_w<<<(1024 * 128) / 256, 256>>>(eWih1, 256, eWih1h, eWih1l);
  pack_w<<<(1024 * 128) / 256, 256>>>(eWhh1, 256, eWhh1h, eWhh1l);
  pack_w<<<(1024 * 16) / 256, 256>>>(dWih0, 32, dWih0h, dWih0l);
  pack_w<<<(1024 * 128) / 256, 256>>>(dWhh0, 256, dWhh0h, dWhh0l);
  pack_w<<<(1024 * 128) / 256, 256>>>(dWih1, 256, dWih1h, dWih1l);
  pack_w<<<(1024 * 128) / 256, 256>>>(dWhh1, 256, dWhh1h, dWhh1l);
  pack_w<<<(1024 * 128) / 256, 256>>>(Wp, 256, Wph, Wpl);

  lstm_persist<<<NCTA, NTHR, SMW * 4>>>(eb0, eb1, db0, db1);
  out_proj<<<dim3(BSZ / 32, TOUT), 256>>>(dWout, dbout, (float*)d_out);
}